// round 1
// baseline (speedup 1.0000x reference)
#include <cuda_runtime.h>

// ---------------------------------------------------------------------------
// Resnet50Encoder: windowed 3D convs decomposed into per-frame 2D convs.
//
// Pipeline:
//   pack_w1 / pack_w2 : reorder conv weights into GEMM A matrices
//   im2col1           : im2col of the 8 video frames  -> B1 (9216 x 1664)
//   sgemm(0)          : F = A1 @ B1  (3072 x 1664)    [24 per-frame 2D convs]
//   combine1          : 25 distinct conv1-relu slices H from sums of F terms
//   im2col2           : im2col of H slices            -> B2 (9216 x 4992)
//   sgemm(1)          : C2 = A2 @ B2 (1536 x 4992)    [75 slice convs]
//   pool              : per (t, ch) max over depth+space of summed C2 terms
//   fc                : 3 small fully-connected layers -> out (8 x 128)
// ---------------------------------------------------------------------------

#define K9   9216          // 1024 * 9 (in_ch * 3x3)
#define M1   3072          // 3 kd * 1024 out_ch
#define N1   1664          // 8 frames * 196, padded to 13*128
#define N1R  1568
#define M2   1536          // 3 kd * 512 out_ch
#define N2   4992          // 25 slices * 196, padded to 39*128
#define NSLICE 25
#define HW   196

// scratch (device globals; no allocations allowed in kernel_launch)
__device__ float d_A1[M1 * K9];
__device__ float d_B1[K9 * N1];
__device__ float d_F [M1 * N1];
__device__ float d_H [NSLICE * 1024 * HW];
__device__ float d_A2[M2 * K9];
__device__ float d_B2[K9 * N2];
__device__ float d_C2[M2 * N2];
__device__ float d_pool[8 * 512];

// ---------------------------------------------------------------- packing --
__global__ void pack_w1_kernel(const float* __restrict__ w) {
    int idx = blockIdx.x * blockDim.x + threadIdx.x;
    if (idx >= M1 * K9) return;
    int k = idx % K9, m = idx / K9;
    int kd = m >> 10, co = m & 1023;
    int ci = k / 9,  r  = k % 9;
    d_A1[idx] = w[co * 27648 + ci * 27 + kd * 9 + r];
}

__global__ void pack_w2_kernel(const float* __restrict__ w) {
    int idx = blockIdx.x * blockDim.x + threadIdx.x;
    if (idx >= M2 * K9) return;
    int k = idx % K9, m = idx / K9;
    int kd = m / 512, co = m % 512;
    int ci = k / 9,  r  = k % 9;
    d_A2[idx] = w[co * 27648 + ci * 27 + kd * 9 + r];
}

// ---------------------------------------------------------------- im2col ---
__global__ void im2col1_kernel(const float* __restrict__ vid) {
    int idx = blockIdx.x * blockDim.x + threadIdx.x;
    if (idx >= K9 * N1) return;
    int n = idx % N1, k = idx / N1;
    float v = 0.0f;
    if (n < N1R) {
        int g  = n / HW, hw = n % HW;
        int y  = hw / 14, x = hw % 14;
        int ci = k / 9,  r = k % 9;
        int kh = r / 3,  kw = r % 3;
        int yy = y + kh - 1, xx = x + kw - 1;
        if (yy >= 0 && yy < 14 && xx >= 0 && xx < 14)
            v = vid[(g * 1024 + ci) * HW + yy * 14 + xx];
    }
    d_B1[idx] = v;
}

__global__ void im2col2_kernel() {
    int idx = blockIdx.x * blockDim.x + threadIdx.x;
    if (idx >= K9 * N2) return;
    int n = idx % N2, k = idx / N2;
    float v = 0.0f;
    if (n < NSLICE * HW) {
        int s  = n / HW, hw = n % HW;
        int y  = hw / 14, x = hw % 14;
        int ci = k / 9,  r = k % 9;
        int kh = r / 3,  kw = r % 3;
        int yy = y + kh - 1, xx = x + kw - 1;
        if (yy >= 0 && yy < 14 && xx >= 0 && xx < 14)
            v = d_H[(s * 1024 + ci) * HW + yy * 14 + xx];
    }
    d_B2[idx] = v;
}

// --------------------------------------------------------- f32x2 helpers ---
__device__ __forceinline__ unsigned long long pk2(float lo, float hi) {
    unsigned long long r;
    asm("mov.b64 %0, {%1, %2};"
        : "=l"(r) : "r"(__float_as_uint(lo)), "r"(__float_as_uint(hi)));
    return r;
}
__device__ __forceinline__ void fma2(unsigned long long& d,
                                     unsigned long long a, unsigned long long b) {
    asm("fma.rn.f32x2 %0, %1, %2, %0;" : "+l"(d) : "l"(a), "l"(b));
}
__device__ __forceinline__ void upk2(unsigned long long v, float& lo, float& hi) {
    unsigned int l, h;
    asm("mov.b64 {%0, %1}, %2;" : "=r"(l), "=r"(h) : "l"(v));
    lo = __uint_as_float(l);
    hi = __uint_as_float(h);
}

// ------------------------------------------------------------------ GEMM ---
// C(MxN) = A(MxK) @ B(KxN), all row-major, M%128==0, N%128==0, K%16==0.
// 128x128 block tile, BK=16, 256 threads, 8x8 microtile (4+4 split),
// f32x2 packed FMAs in the inner loop.
__global__ __launch_bounds__(256, 2) void sgemm_kernel(int which) {
    const float* __restrict__ A = which ? d_A2 : d_A1;
    const float* __restrict__ B = which ? d_B2 : d_B1;
    float*       __restrict__ C = which ? d_C2 : d_F;
    const int N = which ? N2 : N1;
    const int K = K9;

    __shared__ float As[16][128];
    __shared__ float Bs[16][128];

    const int tid = threadIdx.x;
    const int bxn = blockIdx.x * 128;
    const int bym = blockIdx.y * 128;
    const int a_m = tid >> 2;            // 0..63
    const int a_k = (tid & 3) << 2;      // 0,4,8,12
    const int b_k = tid >> 5;            // 0..7
    const int b_n = (tid & 31) << 2;     // 0..124
    const int tx  = tid & 15;
    const int ty  = tid >> 4;

    const float* Ap = A + bym * K;
    const float* Bp = B + bxn;

    unsigned long long acc[8][4];
#pragma unroll
    for (int i = 0; i < 8; i++)
#pragma unroll
        for (int j = 0; j < 4; j++) acc[i][j] = 0ULL;

    for (int k0 = 0; k0 < K; k0 += 16) {
#pragma unroll
        for (int i = 0; i < 2; i++) {
            float4 v = *(const float4*)(Ap + (a_m + i * 64) * K + k0 + a_k);
            As[a_k + 0][a_m + i * 64] = v.x;
            As[a_k + 1][a_m + i * 64] = v.y;
            As[a_k + 2][a_m + i * 64] = v.z;
            As[a_k + 3][a_m + i * 64] = v.w;
        }
#pragma unroll
        for (int i = 0; i < 2; i++) {
            *(float4*)(&Bs[b_k + i * 8][b_n]) =
                *(const float4*)(Bp + (k0 + b_k + i * 8) * N + b_n);
        }
        __syncthreads();

#pragma unroll
        for (int kk = 0; kk < 16; kk++) {
            float4 a0 = *(const float4*)(&As[kk][ty * 4]);
            float4 a1 = *(const float4*)(&As[kk][64 + ty * 4]);
            float4 b0 = *(const float4*)(&Bs[kk][tx * 4]);
            float4 b1 = *(const float4*)(&Bs[kk][64 + tx * 4]);
            unsigned long long bp[4];
            bp[0] = pk2(b0.x, b0.y);
            bp[1] = pk2(b0.z, b0.w);
            bp[2] = pk2(b1.x, b1.y);
            bp[3] = pk2(b1.z, b1.w);
            float ar[8] = {a0.x, a0.y, a0.z, a0.w, a1.x, a1.y, a1.z, a1.w};
#pragma unroll
            for (int i = 0; i < 8; i++) {
                unsigned long long ai = pk2(ar[i], ar[i]);
#pragma unroll
                for (int j = 0; j < 4; j++) fma2(acc[i][j], ai, bp[j]);
            }
        }
        __syncthreads();
    }

#pragma unroll
    for (int i = 0; i < 8; i++) {
        int row = bym + ((i < 4) ? (ty * 4 + i) : (64 + ty * 4 + i - 4));
        float* Cr = C + row * N + bxn;
        float4 v;
        upk2(acc[i][0], v.x, v.y);
        upk2(acc[i][1], v.z, v.w);
        *(float4*)(Cr + tx * 4) = v;
        upk2(acc[i][2], v.x, v.y);
        upk2(acc[i][3], v.z, v.w);
        *(float4*)(Cr + 64 + tx * 4) = v;
    }
}

// --------------------------------------------------------------- combine ---
// 25 distinct conv1 activation slices:
//   s in [0,8):   A_t (window depth 0), t=s:      F[1][t-4] + F[2][t-3]
//   s in [8,17):  G_g (interior),       g=s-12:   F[0][g] + F[1][g+1] + F[2][g+2]
//   s in [17,25): D_t (window depth 3), t=s-17:   F[0][t-2] + F[1][t-1]
// (terms with frame index < 0 are zero; all get +bias then relu)
__global__ void combine1_kernel(const float* __restrict__ b1) {
    int idx = blockIdx.x * blockDim.x + threadIdx.x;
    if (idx >= NSLICE * 1024 * HW) return;
    int hw = idx % HW;
    int t2 = idx / HW;
    int co = t2 & 1023;
    int s  = t2 >> 10;

    int kd[3] = {-1, -1, -1};
    int gg[3] = {0, 0, 0};
    if (s < 8)       { kd[0] = 1; gg[0] = s - 4;  kd[1] = 2; gg[1] = s - 3; }
    else if (s < 17) { int g = s - 12;
                       kd[0] = 0; gg[0] = g; kd[1] = 1; gg[1] = g + 1;
                       kd[2] = 2; gg[2] = g + 2; }
    else             { int t = s - 17;
                       kd[0] = 0; gg[0] = t - 2; kd[1] = 1; gg[1] = t - 1; }

    float v = b1[co];
#pragma unroll
    for (int e = 0; e < 3; e++) {
        if (kd[e] >= 0 && gg[e] >= 0 && gg[e] < 8)
            v += d_F[(kd[e] * 1024 + co) * N1 + gg[e] * HW + hw];
    }
    d_H[idx] = fmaxf(v, 0.0f);
}

// ------------------------------------------------------------------ pool ---
// pooled[t][co] = relu(b2[co] + max over d,hw of sum of conv2 partial slices)
__global__ void pool_kernel(const float* __restrict__ b2) {
    int t  = blockIdx.x >> 9;
    int co = blockIdx.x & 511;
    int s0 = t, s1 = t + 8, s2 = t + 9, s3 = t + 17;
    const float* P0 = d_C2 + (0 * 512 + co) * N2;
    const float* P1 = d_C2 + (1 * 512 + co) * N2;
    const float* P2 = d_C2 + (2 * 512 + co) * N2;

    float m = -1e30f;
    for (int pos = threadIdx.x; pos < 4 * HW; pos += blockDim.x) {
        int d = pos / HW, hw = pos % HW;
        float v;
        if (d == 0)      v = P1[s0 * HW + hw] + P2[s1 * HW + hw];
        else if (d == 1) v = P0[s0 * HW + hw] + P1[s1 * HW + hw] + P2[s2 * HW + hw];
        else if (d == 2) v = P0[s1 * HW + hw] + P1[s2 * HW + hw] + P2[s3 * HW + hw];
        else             v = P0[s2 * HW + hw] + P1[s3 * HW + hw];
        m = fmaxf(m, v);
    }
    __shared__ float red[128];
    red[threadIdx.x] = m;
    __syncthreads();
    for (int sft = 64; sft > 0; sft >>= 1) {
        if (threadIdx.x < sft)
            red[threadIdx.x] = fmaxf(red[threadIdx.x], red[threadIdx.x + sft]);
        __syncthreads();
    }
    if (threadIdx.x == 0)
        d_pool[t * 512 + co] = fmaxf(b2[co] + red[0], 0.0f);
}

// -------------------------------------------------------------------- fc ---
__global__ void fc_kernel(const float* __restrict__ w1, const float* __restrict__ b1,
                          const float* __restrict__ w2, const float* __restrict__ b2,
                          const float* __restrict__ w3, const float* __restrict__ b3,
                          float* __restrict__ out) {
    int t = blockIdx.x;
    int j = threadIdx.x;
    __shared__ float x0[512], x1[512];
    x0[j] = d_pool[t * 512 + j];
    __syncthreads();

    float a = b1[j];
#pragma unroll 8
    for (int i = 0; i < 512; i++) a += x0[i] * w1[j * 512 + i];
    x1[j] = fmaxf(a, 0.0f);
    __syncthreads();

    a = b2[j];
#pragma unroll 8
    for (int i = 0; i < 512; i++) a += x1[i] * w2[j * 512 + i];
    __syncthreads();
    x0[j] = fmaxf(a, 0.0f);
    __syncthreads();

    if (j < 128) {
        a = b3[j];
#pragma unroll 8
        for (int i = 0; i < 512; i++) a += x0[i] * w3[j * 512 + i];
        out[t * 128 + j] = fmaxf(a, 0.0f);
    }
}

// ---------------------------------------------------------------- launch ---
extern "C" void kernel_launch(void* const* d_in, const int* in_sizes, int n_in,
                              void* d_out, int out_size) {
    // size-based input lookup (robust to reordering of distinct sizes;
    // same-size inputs are taken in declared order)
    auto find = [&](int sz, int occ) -> const float* {
        int c = 0;
        for (int i = 0; i < n_in; i++)
            if (in_sizes[i] == sz) { if (c == occ) return (const float*)d_in[i]; c++; }
        return nullptr;
    };
    const float* videos = find(1605632, 0);
    const float* w1     = find(28311552, 0);
    const float* b1     = find(1024, 0);
    const float* w2     = find(14155776, 0);
    const float* b2     = find(512, 0);
    const float* l1w    = find(262144, 0);
    const float* l1b    = find(512, 1);
    const float* l2w    = find(262144, 1);
    const float* l2b    = find(512, 2);
    const float* l3w    = find(65536, 0);
    const float* l3b    = find(128, 0);
    float* out = (float*)d_out;

    const int TB = 256;
    pack_w1_kernel<<<(M1 * K9 + TB - 1) / TB, TB>>>(w1);
    pack_w2_kernel<<<(M2 * K9 + TB - 1) / TB, TB>>>(w2);
    im2col1_kernel<<<(K9 * N1 + TB - 1) / TB, TB>>>(videos);

    dim3 g1(N1 / 128, M1 / 128);
    sgemm_kernel<<<g1, 256>>>(0);

    combine1_kernel<<<(NSLICE * 1024 * HW + TB - 1) / TB, TB>>>(b1);
    im2col2_kernel<<<(K9 * N2 + TB - 1) / TB, TB>>>();

    dim3 g2(N2 / 128, M2 / 128);
    sgemm_kernel<<<g2, 256>>>(1);

    pool_kernel<<<8 * 512, 128>>>(b2);
    fc_kernel<<<8, 512>>>(l1w, l1b, l2w, l2b, l3w, l3b, out);
}

// round 3
// speedup vs baseline: 1.8845x; 1.8845x over previous
#include <cuda_runtime.h>
#include <cuda_bf16.h>
#include <cstdint>

// ---------------------------------------------------------------------------
// Windowed 3D conv encoder. Per-frame 2D conv decomposition + split-bf16
// 3-pass GEMMs on the legacy tensor-core path (mma.sync / ldmatrix /
// cp.async), which compiles on the harness's non-'a' PTX target.
//
//   pack_w1/2 : conv weights -> A [M,K] bf16 hi/lo     (K = 1024*9 = 9216)
//   im2col1   : frames -> B1 [N,K] bf16 hi/lo
//   gemm(0)   : F  = A1 @ B1^T   (3072 x 1664)
//   combine1  : 25 conv1-relu slices H
//   im2col2   : H -> B2 [N,K] bf16 hi/lo
//   gemm(1)   : C2 = A2 @ B2^T   (1536 x 4992)
//   pool, fc  : fp32
// ---------------------------------------------------------------------------

#define K9    9216
#define M1    3072
#define N1R   1568
#define N1P   1664          // 13 * 128
#define M2    1536
#define N2P   4992          // 39 * 128
#define NSLICE 25
#define HW    196
#define BK    32
#define NCH   (K9 / BK)     // 288
#define STAGES 4

// ------------------------------------------------------------- scratch -----
__device__ __nv_bfloat16 d_A1h[M1 * K9];
__device__ __nv_bfloat16 d_A1l[M1 * K9];
__device__ __nv_bfloat16 d_A2h[M2 * K9];
__device__ __nv_bfloat16 d_A2l[M2 * K9];
__device__ __nv_bfloat16 d_B1h[N1P * K9];
__device__ __nv_bfloat16 d_B1l[N1P * K9];
__device__ __nv_bfloat16 d_B2h[N2P * K9];
__device__ __nv_bfloat16 d_B2l[N2P * K9];
__device__ float d_F [M1 * N1P];
__device__ float d_H [NSLICE * 1024 * HW];
__device__ float d_C2[M2 * N2P];
__device__ float d_pool[8 * 512];

// ------------------------------------------------------------ PTX bits -----
__device__ __forceinline__ uint32_t smem_u32(const void* p) {
    uint32_t a;
    asm("{ .reg .u64 t; cvta.to.shared.u64 t, %1; cvt.u32.u64 %0, t; }"
        : "=r"(a) : "l"(p));
    return a;
}
#define CP16(dst, src) \
    asm volatile("cp.async.cg.shared.global [%0], [%1], 16;" \
                 :: "r"(dst), "l"(src))
#define CPCOMMIT() asm volatile("cp.async.commit_group;" ::: "memory")
#define CPWAIT(n)  asm volatile("cp.async.wait_group %0;" :: "n"(n) : "memory")

#define LDSM4(r0, r1, r2, r3, a) \
    asm volatile("ldmatrix.sync.aligned.m8n8.x4.shared.b16 {%0,%1,%2,%3}, [%4];" \
                 : "=r"(r0), "=r"(r1), "=r"(r2), "=r"(r3) : "r"(a))

#define MMA16816(d, a, b0, b1) \
    asm volatile( \
        "mma.sync.aligned.m16n8k16.row.col.f32.bf16.bf16.f32 " \
        "{%0,%1,%2,%3},{%4,%5,%6,%7},{%8,%9},{%0,%1,%2,%3};" \
        : "+f"((d)[0]), "+f"((d)[1]), "+f"((d)[2]), "+f"((d)[3]) \
        : "r"((a)[0]), "r"((a)[1]), "r"((a)[2]), "r"((a)[3]), \
          "r"(b0), "r"(b1))

// ------------------------------------------------------------- packing -----
__device__ __forceinline__ void split_write(float v, __nv_bfloat16* h,
                                            __nv_bfloat16* l, size_t idx) {
    __nv_bfloat16 hi = __float2bfloat16_rn(v);
    h[idx] = hi;
    l[idx] = __float2bfloat16_rn(v - __bfloat162float(hi));
}

__global__ void pack_w1_kernel(const float* __restrict__ w) {
    int idx = blockIdx.x * blockDim.x + threadIdx.x;
    if (idx >= M1 * K9) return;
    int k = idx % K9, m = idx / K9;
    int kd = m >> 10, co = m & 1023;
    int ci = k / 9,  r  = k % 9;
    split_write(w[co * 27648 + ci * 27 + kd * 9 + r], d_A1h, d_A1l, idx);
}

__global__ void pack_w2_kernel(const float* __restrict__ w) {
    int idx = blockIdx.x * blockDim.x + threadIdx.x;
    if (idx >= M2 * K9) return;
    int k = idx % K9, m = idx / K9;
    int kd = m / 512, co = m % 512;
    int ci = k / 9,  r  = k % 9;
    split_write(w[co * 27648 + ci * 27 + kd * 9 + r], d_A2h, d_A2l, idx);
}

// ------------------------------------------------------------- im2col ------
__global__ void im2col1_kernel(const float* __restrict__ vid) {
    size_t idx = (size_t)blockIdx.x * blockDim.x + threadIdx.x;
    if (idx >= (size_t)N1P * K9) return;
    int k = idx % K9, n = idx / K9;
    float v = 0.0f;
    if (n < N1R) {
        int g  = n / HW, hw = n % HW;
        int y  = hw / 14, x = hw % 14;
        int ci = k / 9,  r = k % 9;
        int kh = r / 3,  kw = r % 3;
        int yy = y + kh - 1, xx = x + kw - 1;
        if (yy >= 0 && yy < 14 && xx >= 0 && xx < 14)
            v = vid[(g * 1024 + ci) * HW + yy * 14 + xx];
    }
    split_write(v, d_B1h, d_B1l, idx);
}

__global__ void im2col2_kernel() {
    size_t idx = (size_t)blockIdx.x * blockDim.x + threadIdx.x;
    if (idx >= (size_t)N2P * K9) return;
    int k = idx % K9, n = idx / K9;
    float v = 0.0f;
    if (n < NSLICE * HW) {
        int s  = n / HW, hw = n % HW;
        int y  = hw / 14, x = hw % 14;
        int ci = k / 9,  r = k % 9;
        int kh = r / 3,  kw = r % 3;
        int yy = y + kh - 1, xx = x + kw - 1;
        if (yy >= 0 && yy < 14 && xx >= 0 && xx < 14)
            v = d_H[(size_t)(s * 1024 + ci) * HW + yy * 14 + xx];
    }
    split_write(v, d_B2h, d_B2l, idx);
}

// --------------------------------------------------------------- GEMM ------
// C(M x Np) = A(M x K) @ B(Np x K)^T, split-bf16 3-pass fused in k-loop.
// 128x128 CTA tile, 8 warps as 4(m) x 2(n) -> warp tile 32x64.
// SMEM stage: Ah | Al | Bh | Bl, each 128 rows x 32 cols, row stride 40 elems.
#define RS        40                        // padded row stride (elements)
#define TILE_B    (128 * RS * 2)            // 10240 bytes per matrix
#define OFF_AH    0
#define OFF_AL    (1 * TILE_B)
#define OFF_BH    (2 * TILE_B)
#define OFF_BL    (3 * TILE_B)
#define STG_B     (4 * TILE_B)              // 40960 bytes per stage
#define SMEM_TOTAL (STAGES * STG_B)         // 163840

__global__ __launch_bounds__(256, 1) void gemm_mma(int which) {
    const __nv_bfloat16* __restrict__ Ah = which ? d_A2h : d_A1h;
    const __nv_bfloat16* __restrict__ Al = which ? d_A2l : d_A1l;
    const __nv_bfloat16* __restrict__ Bh = which ? d_B2h : d_B1h;
    const __nv_bfloat16* __restrict__ Bl = which ? d_B2l : d_B1l;
    float* __restrict__ C = which ? d_C2 : d_F;
    const int Np = which ? N2P : N1P;

    extern __shared__ char smem[];
    const uint32_t smb = smem_u32(smem);
    const int tid  = threadIdx.x;
    const int lane = tid & 31;
    const int wid  = tid >> 5;
    const int wm   = wid >> 1;              // 0..3
    const int wn   = wid & 1;               // 0..1
    const int bym  = blockIdx.y * 128;
    const int bxn  = blockIdx.x * 128;

    const __nv_bfloat16* pAh = Ah + (size_t)bym * K9;
    const __nv_bfloat16* pAl = Al + (size_t)bym * K9;
    const __nv_bfloat16* pBh = Bh + (size_t)bxn * K9;
    const __nv_bfloat16* pBl = Bl + (size_t)bxn * K9;

    // cp.async geometry: 512 16B-chunks per matrix; 2 per thread.
    int ldRow[2], ldC16[2];
#pragma unroll
    for (int t = 0; t < 2; t++) {
        int q = tid + 256 * t;
        ldRow[t] = q >> 2;
        ldC16[t] = q & 3;
    }

    auto issue_stage = [&](int stage, int k0) {
        uint32_t sb = smb + stage * STG_B;
#pragma unroll
        for (int t = 0; t < 2; t++) {
            size_t   so = (size_t)ldRow[t] * K9 + k0 + ldC16[t] * 8;
            uint32_t dofs = ldRow[t] * (RS * 2) + ldC16[t] * 16;
            CP16(sb + OFF_AH + dofs, pAh + so);
            CP16(sb + OFF_AL + dofs, pAl + so);
            CP16(sb + OFF_BH + dofs, pBh + so);
            CP16(sb + OFF_BL + dofs, pBl + so);
        }
        CPCOMMIT();
    };

    float acc[2][8][4];
#pragma unroll
    for (int mt = 0; mt < 2; mt++)
#pragma unroll
        for (int nt = 0; nt < 8; nt++)
#pragma unroll
            for (int i = 0; i < 4; i++) acc[mt][nt][i] = 0.0f;

    // ldmatrix lane addressing (byte offsets within a tile matrix)
    const int a_row = wm * 32 + (lane & 15);
    const int a_kof = (lane >> 4) * 8;
    const int b_row = wn * 64 + ((lane >> 4) & 1) * 8 + (lane & 7);
    const int b_kof = ((lane >> 3) & 1) * 8;

#pragma unroll
    for (int s = 0; s < STAGES - 1; s++) issue_stage(s, s * BK);

    for (int it = 0; it < NCH; it++) {
        if (it + STAGES - 1 < NCH)
            issue_stage((it + STAGES - 1) & (STAGES - 1), (it + STAGES - 1) * BK);
        else
            CPCOMMIT();
        CPWAIT(STAGES - 1);
        __syncthreads();

        uint32_t sb = smb + (it & (STAGES - 1)) * STG_B;
#pragma unroll
        for (int ks = 0; ks < 2; ks++) {
            uint32_t ah[2][4], al[2][4], bh[4][4], bl[4][4];
#pragma unroll
            for (int mt = 0; mt < 2; mt++) {
                uint32_t ao = (a_row + mt * 16) * (RS * 2)
                            + (ks * 16 + a_kof) * 2;
                LDSM4(ah[mt][0], ah[mt][1], ah[mt][2], ah[mt][3], sb + OFF_AH + ao);
                LDSM4(al[mt][0], al[mt][1], al[mt][2], al[mt][3], sb + OFF_AL + ao);
            }
#pragma unroll
            for (int g = 0; g < 4; g++) {
                uint32_t bo = (b_row + g * 16) * (RS * 2)
                            + (ks * 16 + b_kof) * 2;
                LDSM4(bh[g][0], bh[g][1], bh[g][2], bh[g][3], sb + OFF_BH + bo);
                LDSM4(bl[g][0], bl[g][1], bl[g][2], bl[g][3], sb + OFF_BL + bo);
            }
#pragma unroll
            for (int mt = 0; mt < 2; mt++)
#pragma unroll
                for (int nt = 0; nt < 8; nt++) {
                    int g = nt >> 1, o = (nt & 1) * 2;
                    MMA16816(acc[mt][nt], ah[mt], bh[g][o], bh[g][o + 1]);
                    MMA16816(acc[mt][nt], ah[mt], bl[g][o], bl[g][o + 1]);
                    MMA16816(acc[mt][nt], al[mt], bh[g][o], bh[g][o + 1]);
                }
        }
        __syncthreads();
    }

    // epilogue
#pragma unroll
    for (int mt = 0; mt < 2; mt++) {
        int r0 = bym + wm * 32 + mt * 16 + (lane >> 2);
#pragma unroll
        for (int nt = 0; nt < 8; nt++) {
            int c0 = bxn + wn * 64 + nt * 8 + (lane & 3) * 2;
            *(float2*)(C + (size_t)r0 * Np + c0) =
                make_float2(acc[mt][nt][0], acc[mt][nt][1]);
            *(float2*)(C + (size_t)(r0 + 8) * Np + c0) =
                make_float2(acc[mt][nt][2], acc[mt][nt][3]);
        }
    }
}

// ------------------------------------------------------------- combine -----
__global__ void combine1_kernel(const float* __restrict__ b1) {
    int idx = blockIdx.x * blockDim.x + threadIdx.x;
    if (idx >= NSLICE * 1024 * HW) return;
    int hw = idx % HW;
    int t2 = idx / HW;
    int co = t2 & 1023;
    int s  = t2 >> 10;

    int kd[3] = {-1, -1, -1};
    int gg[3] = {0, 0, 0};
    if (s < 8)       { kd[0] = 1; gg[0] = s - 4;  kd[1] = 2; gg[1] = s - 3; }
    else if (s < 17) { int g = s - 12;
                       kd[0] = 0; gg[0] = g; kd[1] = 1; gg[1] = g + 1;
                       kd[2] = 2; gg[2] = g + 2; }
    else             { int t = s - 17;
                       kd[0] = 0; gg[0] = t - 2; kd[1] = 1; gg[1] = t - 1; }

    float v = b1[co];
#pragma unroll
    for (int e = 0; e < 3; e++) {
        if (kd[e] >= 0 && gg[e] >= 0 && gg[e] < 8)
            v += d_F[(size_t)(kd[e] * 1024 + co) * N1P + gg[e] * HW + hw];
    }
    d_H[idx] = fmaxf(v, 0.0f);
}

// ---------------------------------------------------------------- pool -----
__global__ void pool_kernel(const float* __restrict__ b2) {
    int t  = blockIdx.x >> 9;
    int co = blockIdx.x & 511;
    int s0 = t, s1 = t + 8, s2 = t + 9, s3 = t + 17;
    const float* P0 = d_C2 + (size_t)(0 * 512 + co) * N2P;
    const float* P1 = d_C2 + (size_t)(1 * 512 + co) * N2P;
    const float* P2 = d_C2 + (size_t)(2 * 512 + co) * N2P;

    float m = -1e30f;
    for (int pos = threadIdx.x; pos < 4 * HW; pos += blockDim.x) {
        int d = pos / HW, hw = pos % HW;
        float v;
        if (d == 0)      v = P1[s0 * HW + hw] + P2[s1 * HW + hw];
        else if (d == 1) v = P0[s0 * HW + hw] + P1[s1 * HW + hw] + P2[s2 * HW + hw];
        else if (d == 2) v = P0[s1 * HW + hw] + P1[s2 * HW + hw] + P2[s3 * HW + hw];
        else             v = P0[s2 * HW + hw] + P1[s3 * HW + hw];
        m = fmaxf(m, v);
    }
    __shared__ float red[128];
    red[threadIdx.x] = m;
    __syncthreads();
    for (int sft = 64; sft > 0; sft >>= 1) {
        if (threadIdx.x < sft)
            red[threadIdx.x] = fmaxf(red[threadIdx.x], red[threadIdx.x + sft]);
        __syncthreads();
    }
    if (threadIdx.x == 0)
        d_pool[t * 512 + co] = fmaxf(b2[co] + red[0], 0.0f);
}

// ------------------------------------------------------------------ fc -----
__global__ void fc_kernel(const float* __restrict__ w1, const float* __restrict__ b1,
                          const float* __restrict__ w2, const float* __restrict__ b2,
                          const float* __restrict__ w3, const float* __restrict__ b3,
                          float* __restrict__ out) {
    int t = blockIdx.x;
    int j = threadIdx.x;
    __shared__ float x0[512], x1[512];
    x0[j] = d_pool[t * 512 + j];
    __syncthreads();

    float a = b1[j];
#pragma unroll 8
    for (int i = 0; i < 512; i++) a += x0[i] * w1[j * 512 + i];
    x1[j] = fmaxf(a, 0.0f);
    __syncthreads();

    a = b2[j];
#pragma unroll 8
    for (int i = 0; i < 512; i++) a += x1[i] * w2[j * 512 + i];
    __syncthreads();
    x0[j] = fmaxf(a, 0.0f);
    __syncthreads();

    if (j < 128) {
        a = b3[j];
#pragma unroll 8
        for (int i = 0; i < 512; i++) a += x0[i] * w3[j * 512 + i];
        out[t * 128 + j] = fmaxf(a, 0.0f);
    }
}

// -------------------------------------------------------------- launch -----
extern "C" void kernel_launch(void* const* d_in, const int* in_sizes, int n_in,
                              void* d_out, int out_size) {
    auto find = [&](int sz, int occ) -> const float* {
        int c = 0;
        for (int i = 0; i < n_in; i++)
            if (in_sizes[i] == sz) { if (c == occ) return (const float*)d_in[i]; c++; }
        return nullptr;
    };
    const float* videos = find(1605632, 0);
    const float* w1     = find(28311552, 0);
    const float* b1     = find(1024, 0);
    const float* w2     = find(14155776, 0);
    const float* b2     = find(512, 0);
    const float* l1w    = find(262144, 0);
    const float* l1b    = find(512, 1);
    const float* l2w    = find(262144, 1);
    const float* l2b    = find(512, 2);
    const float* l3w    = find(65536, 0);
    const float* l3b    = find(128, 0);
    float* out = (float*)d_out;

    cudaFuncSetAttribute(gemm_mma, cudaFuncAttributeMaxDynamicSharedMemorySize,
                         SMEM_TOTAL);

    const int TB = 256;
    pack_w1_kernel<<<(M1 * K9 + TB - 1) / TB, TB>>>(w1);
    pack_w2_kernel<<<(M2 * K9 + TB - 1) / TB, TB>>>(w2);
    im2col1_kernel<<<(int)(((size_t)N1P * K9 + TB - 1) / TB), TB>>>(videos);

    gemm_mma<<<dim3(N1P / 128, M1 / 128), 256, SMEM_TOTAL>>>(0);

    combine1_kernel<<<(NSLICE * 1024 * HW + TB - 1) / TB, TB>>>(b1);
    im2col2_kernel<<<(int)(((size_t)N2P * K9 + TB - 1) / TB), TB>>>();

    gemm_mma<<<dim3(N2P / 128, M2 / 128), 256, SMEM_TOTAL>>>(1);

    pool_kernel<<<8 * 512, 128>>>(b2);
    fc_kernel<<<8, 512>>>(l1w, l1b, l2w, l2b, l3w, l3b, out);
}

// round 4
// speedup vs baseline: 2.0277x; 1.0760x over previous
#include <cuda_runtime.h>
#include <cuda_bf16.h>
#include <cstdint>

// ---------------------------------------------------------------------------
// Windowed 3D conv encoder. Per-frame 2D conv decomposition + split-bf16
// 3-pass GEMMs on mma.sync/ldmatrix/cp.async (compiles on non-'a' target).
// R4: 128x64 CTA tile, 3 stages, 2 CTAs/SM, single sync per k-iter.
// ---------------------------------------------------------------------------

#define K9    9216
#define M1    3072
#define N1R   1568
#define N1P   1664          // 26 * 64
#define M2    1536
#define N2P   4992          // 78 * 64
#define NSLICE 25
#define HW    196
#define BK    32
#define NCH   (K9 / BK)     // 288
#define STAGES 3

// ------------------------------------------------------------- scratch -----
__device__ __nv_bfloat16 d_A1h[M1 * K9];
__device__ __nv_bfloat16 d_A1l[M1 * K9];
__device__ __nv_bfloat16 d_A2h[M2 * K9];
__device__ __nv_bfloat16 d_A2l[M2 * K9];
__device__ __nv_bfloat16 d_B1h[N1P * K9];
__device__ __nv_bfloat16 d_B1l[N1P * K9];
__device__ __nv_bfloat16 d_B2h[N2P * K9];
__device__ __nv_bfloat16 d_B2l[N2P * K9];
__device__ float d_F [M1 * N1P];
__device__ float d_H [NSLICE * 1024 * HW];
__device__ float d_C2[M2 * N2P];
__device__ float d_pool[8 * 512];

// ------------------------------------------------------------ PTX bits -----
__device__ __forceinline__ uint32_t smem_u32(const void* p) {
    uint32_t a;
    asm("{ .reg .u64 t; cvta.to.shared.u64 t, %1; cvt.u32.u64 %0, t; }"
        : "=r"(a) : "l"(p));
    return a;
}
#define CP16(dst, src) \
    asm volatile("cp.async.cg.shared.global [%0], [%1], 16;" \
                 :: "r"(dst), "l"(src))
#define CPCOMMIT() asm volatile("cp.async.commit_group;" ::: "memory")
#define CPWAIT(n)  asm volatile("cp.async.wait_group %0;" :: "n"(n) : "memory")

#define LDSM4(r0, r1, r2, r3, a) \
    asm volatile("ldmatrix.sync.aligned.m8n8.x4.shared.b16 {%0,%1,%2,%3}, [%4];" \
                 : "=r"(r0), "=r"(r1), "=r"(r2), "=r"(r3) : "r"(a))

#define MMA16816(d, a, b0, b1) \
    asm volatile( \
        "mma.sync.aligned.m16n8k16.row.col.f32.bf16.bf16.f32 " \
        "{%0,%1,%2,%3},{%4,%5,%6,%7},{%8,%9},{%0,%1,%2,%3};" \
        : "+f"((d)[0]), "+f"((d)[1]), "+f"((d)[2]), "+f"((d)[3]) \
        : "r"((a)[0]), "r"((a)[1]), "r"((a)[2]), "r"((a)[3]), \
          "r"(b0), "r"(b1))

// ------------------------------------------------------------- packing -----
__device__ __forceinline__ void split_write(float v, __nv_bfloat16* h,
                                            __nv_bfloat16* l, size_t idx) {
    __nv_bfloat16 hi = __float2bfloat16_rn(v);
    h[idx] = hi;
    l[idx] = __float2bfloat16_rn(v - __bfloat162float(hi));
}

__global__ void pack_w1_kernel(const float* __restrict__ w) {
    int idx = blockIdx.x * blockDim.x + threadIdx.x;
    if (idx >= M1 * K9) return;
    int k = idx % K9, m = idx / K9;
    int kd = m >> 10, co = m & 1023;
    int ci = k / 9,  r  = k % 9;
    split_write(w[co * 27648 + ci * 27 + kd * 9 + r], d_A1h, d_A1l, idx);
}

__global__ void pack_w2_kernel(const float* __restrict__ w) {
    int idx = blockIdx.x * blockDim.x + threadIdx.x;
    if (idx >= M2 * K9) return;
    int k = idx % K9, m = idx / K9;
    int kd = m / 512, co = m % 512;
    int ci = k / 9,  r  = k % 9;
    split_write(w[co * 27648 + ci * 27 + kd * 9 + r], d_A2h, d_A2l, idx);
}

// ------------------------------------------------------------- im2col ------
__global__ void im2col1_kernel(const float* __restrict__ vid) {
    size_t idx = (size_t)blockIdx.x * blockDim.x + threadIdx.x;
    if (idx >= (size_t)N1P * K9) return;
    int k = idx % K9, n = idx / K9;
    float v = 0.0f;
    if (n < N1R) {
        int g  = n / HW, hw = n % HW;
        int y  = hw / 14, x = hw % 14;
        int ci = k / 9,  r = k % 9;
        int kh = r / 3,  kw = r % 3;
        int yy = y + kh - 1, xx = x + kw - 1;
        if (yy >= 0 && yy < 14 && xx >= 0 && xx < 14)
            v = vid[(g * 1024 + ci) * HW + yy * 14 + xx];
    }
    split_write(v, d_B1h, d_B1l, idx);
}

__global__ void im2col2_kernel() {
    size_t idx = (size_t)blockIdx.x * blockDim.x + threadIdx.x;
    if (idx >= (size_t)N2P * K9) return;
    int k = idx % K9, n = idx / K9;
    float v = 0.0f;
    if (n < NSLICE * HW) {
        int s  = n / HW, hw = n % HW;
        int y  = hw / 14, x = hw % 14;
        int ci = k / 9,  r = k % 9;
        int kh = r / 3,  kw = r % 3;
        int yy = y + kh - 1, xx = x + kw - 1;
        if (yy >= 0 && yy < 14 && xx >= 0 && xx < 14)
            v = d_H[(size_t)(s * 1024 + ci) * HW + yy * 14 + xx];
    }
    split_write(v, d_B2h, d_B2l, idx);
}

// --------------------------------------------------------------- GEMM ------
// C(M x Np) = A(M x K) @ B(Np x K)^T, split-bf16 3-pass fused in k-loop.
// 128x64 CTA tile, 8 warps as 4(m) x 2(n) -> warp tile 32x32.
// Stage: Ah | Al (128x32, RS=40) | Bh | Bl (64x32, RS=40). 3 stages = 90KB.
#define RS        40
#define A_TILE_B  (128 * RS * 2)            // 10240
#define B_TILE_B  (64 * RS * 2)             // 5120
#define OFF_AH    0
#define OFF_AL    (A_TILE_B)
#define OFF_BH    (2 * A_TILE_B)
#define OFF_BL    (2 * A_TILE_B + B_TILE_B)
#define STG_B     (2 * A_TILE_B + 2 * B_TILE_B)   // 30720
#define SMEM_TOTAL (STAGES * STG_B)               // 92160

__global__ __launch_bounds__(256, 2) void gemm_mma(int which) {
    const __nv_bfloat16* __restrict__ Ah = which ? d_A2h : d_A1h;
    const __nv_bfloat16* __restrict__ Al = which ? d_A2l : d_A1l;
    const __nv_bfloat16* __restrict__ Bh = which ? d_B2h : d_B1h;
    const __nv_bfloat16* __restrict__ Bl = which ? d_B2l : d_B1l;
    float* __restrict__ C = which ? d_C2 : d_F;
    const int Np = which ? N2P : N1P;

    extern __shared__ char smem[];
    const uint32_t smb = smem_u32(smem);
    const int tid  = threadIdx.x;
    const int lane = tid & 31;
    const int wid  = tid >> 5;
    const int wm   = wid >> 1;              // 0..3
    const int wn   = wid & 1;               // 0..1
    const int bym  = blockIdx.y * 128;
    const int bxn  = blockIdx.x * 64;

    const __nv_bfloat16* pAh = Ah + (size_t)bym * K9;
    const __nv_bfloat16* pAl = Al + (size_t)bym * K9;
    const __nv_bfloat16* pBh = Bh + (size_t)bxn * K9;
    const __nv_bfloat16* pBl = Bl + (size_t)bxn * K9;

    // cp.async geometry: A 512 chunks (2/thread), B 256 chunks (1/thread)
    const int aRow0 = (tid * 2)     >> 2, aC0 = (tid * 2)     & 3;
    const int aRow1 = (tid * 2 + 1) >> 2, aC1 = (tid * 2 + 1) & 3;
    const int bRow  = tid >> 2,           bC  = tid & 3;

    auto issue_stage = [&](int stage, int k0) {
        uint32_t sb = smb + stage * STG_B;
        size_t   sa0 = (size_t)aRow0 * K9 + k0 + aC0 * 8;
        size_t   sa1 = (size_t)aRow1 * K9 + k0 + aC1 * 8;
        size_t   sb0 = (size_t)bRow  * K9 + k0 + bC  * 8;
        uint32_t da0 = aRow0 * (RS * 2) + aC0 * 16;
        uint32_t da1 = aRow1 * (RS * 2) + aC1 * 16;
        uint32_t db0 = bRow  * (RS * 2) + bC  * 16;
        CP16(sb + OFF_AH + da0, pAh + sa0);
        CP16(sb + OFF_AH + da1, pAh + sa1);
        CP16(sb + OFF_AL + da0, pAl + sa0);
        CP16(sb + OFF_AL + da1, pAl + sa1);
        CP16(sb + OFF_BH + db0, pBh + sb0);
        CP16(sb + OFF_BL + db0, pBl + sb0);
        CPCOMMIT();
    };

    float acc[2][4][4];
#pragma unroll
    for (int mt = 0; mt < 2; mt++)
#pragma unroll
        for (int nt = 0; nt < 4; nt++)
#pragma unroll
            for (int i = 0; i < 4; i++) acc[mt][nt][i] = 0.0f;

    const int a_row = wm * 32 + (lane & 15);
    const int a_kof = (lane >> 4) * 8;
    const int b_row = wn * 32 + ((lane >> 4) & 1) * 8 + (lane & 7);
    const int b_kof = ((lane >> 3) & 1) * 8;

    issue_stage(0, 0);
    issue_stage(1, BK);

    int stage = 0;
    for (int it = 0; it < NCH; it++) {
        if (it + 1 < NCH) { CPWAIT(1); } else { CPWAIT(0); }
        __syncthreads();
        if (it + 2 < NCH) {
            int ws = stage + 2; if (ws >= STAGES) ws -= STAGES;
            issue_stage(ws, (it + 2) * BK);
        }

        uint32_t sb = smb + stage * STG_B;
#pragma unroll
        for (int ks = 0; ks < 2; ks++) {
            uint32_t ah[2][4], al[2][4], bh[2][4], bl[2][4];
#pragma unroll
            for (int mt = 0; mt < 2; mt++) {
                uint32_t ao = (a_row + mt * 16) * (RS * 2)
                            + (ks * 16 + a_kof) * 2;
                LDSM4(ah[mt][0], ah[mt][1], ah[mt][2], ah[mt][3], sb + OFF_AH + ao);
                LDSM4(al[mt][0], al[mt][1], al[mt][2], al[mt][3], sb + OFF_AL + ao);
            }
#pragma unroll
            for (int g = 0; g < 2; g++) {
                uint32_t bo = (b_row + g * 16) * (RS * 2)
                            + (ks * 16 + b_kof) * 2;
                LDSM4(bh[g][0], bh[g][1], bh[g][2], bh[g][3], sb + OFF_BH + bo);
                LDSM4(bl[g][0], bl[g][1], bl[g][2], bl[g][3], sb + OFF_BL + bo);
            }
#pragma unroll
            for (int mt = 0; mt < 2; mt++)
#pragma unroll
                for (int nt = 0; nt < 4; nt++) {
                    int g = nt >> 1, o = (nt & 1) * 2;
                    MMA16816(acc[mt][nt], ah[mt], bh[g][o], bh[g][o + 1]);
                    MMA16816(acc[mt][nt], ah[mt], bl[g][o], bl[g][o + 1]);
                    MMA16816(acc[mt][nt], al[mt], bh[g][o], bh[g][o + 1]);
                }
        }
        __syncthreads();
        if (++stage == STAGES) stage = 0;
    }

    // epilogue
#pragma unroll
    for (int mt = 0; mt < 2; mt++) {
        int r0 = bym + wm * 32 + mt * 16 + (lane >> 2);
#pragma unroll
        for (int nt = 0; nt < 4; nt++) {
            int c0 = bxn + wn * 32 + nt * 8 + (lane & 3) * 2;
            *(float2*)(C + (size_t)r0 * Np + c0) =
                make_float2(acc[mt][nt][0], acc[mt][nt][1]);
            *(float2*)(C + (size_t)(r0 + 8) * Np + c0) =
                make_float2(acc[mt][nt][2], acc[mt][nt][3]);
        }
    }
}

// ------------------------------------------------------------- combine -----
__global__ void combine1_kernel(const float* __restrict__ b1) {
    int idx = blockIdx.x * blockDim.x + threadIdx.x;
    if (idx >= NSLICE * 1024 * HW) return;
    int hw = idx % HW;
    int t2 = idx / HW;
    int co = t2 & 1023;
    int s  = t2 >> 10;

    int kd[3] = {-1, -1, -1};
    int gg[3] = {0, 0, 0};
    if (s < 8)       { kd[0] = 1; gg[0] = s - 4;  kd[1] = 2; gg[1] = s - 3; }
    else if (s < 17) { int g = s - 12;
                       kd[0] = 0; gg[0] = g; kd[1] = 1; gg[1] = g + 1;
                       kd[2] = 2; gg[2] = g + 2; }
    else             { int t = s - 17;
                       kd[0] = 0; gg[0] = t - 2; kd[1] = 1; gg[1] = t - 1; }

    float v = b1[co];
#pragma unroll
    for (int e = 0; e < 3; e++) {
        if (kd[e] >= 0 && gg[e] >= 0 && gg[e] < 8)
            v += d_F[(size_t)(kd[e] * 1024 + co) * N1P + gg[e] * HW + hw];
    }
    d_H[idx] = fmaxf(v, 0.0f);
}

// ---------------------------------------------------------------- pool -----
__global__ void pool_kernel(const float* __restrict__ b2) {
    int t  = blockIdx.x >> 9;
    int co = blockIdx.x & 511;
    int s0 = t, s1 = t + 8, s2 = t + 9, s3 = t + 17;
    const float* P0 = d_C2 + (size_t)(0 * 512 + co) * N2P;
    const float* P1 = d_C2 + (size_t)(1 * 512 + co) * N2P;
    const float* P2 = d_C2 + (size_t)(2 * 512 + co) * N2P;

    float m = -1e30f;
    for (int pos = threadIdx.x; pos < 4 * HW; pos += blockDim.x) {
        int d = pos / HW, hw = pos % HW;
        float v;
        if (d == 0)      v = P1[s0 * HW + hw] + P2[s1 * HW + hw];
        else if (d == 1) v = P0[s0 * HW + hw] + P1[s1 * HW + hw] + P2[s2 * HW + hw];
        else if (d == 2) v = P0[s1 * HW + hw] + P1[s2 * HW + hw] + P2[s3 * HW + hw];
        else             v = P0[s2 * HW + hw] + P1[s3 * HW + hw];
        m = fmaxf(m, v);
    }
    __shared__ float red[128];
    red[threadIdx.x] = m;
    __syncthreads();
    for (int sft = 64; sft > 0; sft >>= 1) {
        if (threadIdx.x < sft)
            red[threadIdx.x] = fmaxf(red[threadIdx.x], red[threadIdx.x + sft]);
        __syncthreads();
    }
    if (threadIdx.x == 0)
        d_pool[t * 512 + co] = fmaxf(b2[co] + red[0], 0.0f);
}

// ------------------------------------------------------------------ fc -----
__global__ void fc_kernel(const float* __restrict__ w1, const float* __restrict__ b1,
                          const float* __restrict__ w2, const float* __restrict__ b2,
                          const float* __restrict__ w3, const float* __restrict__ b3,
                          float* __restrict__ out) {
    int t = blockIdx.x;
    int j = threadIdx.x;
    __shared__ float x0[512], x1[512];
    x0[j] = d_pool[t * 512 + j];
    __syncthreads();

    float a = b1[j];
#pragma unroll 8
    for (int i = 0; i < 512; i++) a += x0[i] * w1[j * 512 + i];
    x1[j] = fmaxf(a, 0.0f);
    __syncthreads();

    a = b2[j];
#pragma unroll 8
    for (int i = 0; i < 512; i++) a += x1[i] * w2[j * 512 + i];
    __syncthreads();
    x0[j] = fmaxf(a, 0.0f);
    __syncthreads();

    if (j < 128) {
        a = b3[j];
#pragma unroll 8
        for (int i = 0; i < 512; i++) a += x0[i] * w3[j * 512 + i];
        out[t * 128 + j] = fmaxf(a, 0.0f);
    }
}

// -------------------------------------------------------------- launch -----
extern "C" void kernel_launch(void* const* d_in, const int* in_sizes, int n_in,
                              void* d_out, int out_size) {
    auto find = [&](int sz, int occ) -> const float* {
        int c = 0;
        for (int i = 0; i < n_in; i++)
            if (in_sizes[i] == sz) { if (c == occ) return (const float*)d_in[i]; c++; }
        return nullptr;
    };
    const float* videos = find(1605632, 0);
    const float* w1     = find(28311552, 0);
    const float* b1     = find(1024, 0);
    const float* w2     = find(14155776, 0);
    const float* b2     = find(512, 0);
    const float* l1w    = find(262144, 0);
    const float* l1b    = find(512, 1);
    const float* l2w    = find(262144, 1);
    const float* l2b    = find(512, 2);
    const float* l3w    = find(65536, 0);
    const float* l3b    = find(128, 0);
    float* out = (float*)d_out;

    cudaFuncSetAttribute(gemm_mma, cudaFuncAttributeMaxDynamicSharedMemorySize,
                         SMEM_TOTAL);

    const int TB = 256;
    pack_w1_kernel<<<(M1 * K9 + TB - 1) / TB, TB>>>(w1);
    pack_w2_kernel<<<(M2 * K9 + TB - 1) / TB, TB>>>(w2);
    im2col1_kernel<<<(int)(((size_t)N1P * K9 + TB - 1) / TB), TB>>>(videos);

    gemm_mma<<<dim3(N1P / 64, M1 / 128), 256, SMEM_TOTAL>>>(0);

    combine1_kernel<<<(NSLICE * 1024 * HW + TB - 1) / TB, TB>>>(b1);
    im2col2_kernel<<<(int)(((size_t)N2P * K9 + TB - 1) / TB), TB>>>();

    gemm_mma<<<dim3(N2P / 64, M2 / 128), 256, SMEM_TOTAL>>>(1);

    pool_kernel<<<8 * 512, 128>>>(b2);
    fc_kernel<<<8, 512>>>(l1w, l1b, l2w, l2b, l3w, l3b, out);
}

// round 6
// speedup vs baseline: 2.4085x; 1.1878x over previous
#include <cuda_runtime.h>
#include <cuda_bf16.h>
#include <cstdint>

// ---------------------------------------------------------------------------
// Windowed 3D conv encoder. Per-frame 2D conv decomposition + split-bf16
// 3-pass GEMMs on mma.sync/ldmatrix/cp.async.
// R6: 128x128 CTA tile, 8 warps (4m x 2n, warp 32x64), 3 stages,
//     XOR-swizzled 64B rows (no padding) -> 96KB/CTA -> 2 CTAs/SM,
//     single __syncthreads per k-iteration.
// ---------------------------------------------------------------------------

#define K9    9216
#define M1    3072
#define N1R   1568
#define N1P   1664          // 13 * 128
#define M2    1536
#define N2P   4992          // 39 * 128
#define NSLICE 25
#define HW    196
#define BK    32
#define NCH   (K9 / BK)     // 288
#define STAGES 3

// ------------------------------------------------------------- scratch -----
__device__ __nv_bfloat16 d_A1h[M1 * K9];
__device__ __nv_bfloat16 d_A1l[M1 * K9];
__device__ __nv_bfloat16 d_A2h[M2 * K9];
__device__ __nv_bfloat16 d_A2l[M2 * K9];
__device__ __nv_bfloat16 d_B1h[N1P * K9];
__device__ __nv_bfloat16 d_B1l[N1P * K9];
__device__ __nv_bfloat16 d_B2h[N2P * K9];
__device__ __nv_bfloat16 d_B2l[N2P * K9];
__device__ float d_F [M1 * N1P];
__device__ float d_H [NSLICE * 1024 * HW];
__device__ float d_C2[M2 * N2P];
__device__ float d_pool[8 * 512];

// ------------------------------------------------------------ PTX bits -----
__device__ __forceinline__ uint32_t smem_u32(const void* p) {
    uint32_t a;
    asm("{ .reg .u64 t; cvta.to.shared.u64 t, %1; cvt.u32.u64 %0, t; }"
        : "=r"(a) : "l"(p));
    return a;
}
#define CP16(dst, src) \
    asm volatile("cp.async.cg.shared.global [%0], [%1], 16;" \
                 :: "r"(dst), "l"(src))
#define CPCOMMIT() asm volatile("cp.async.commit_group;" ::: "memory")
#define CPWAIT(n)  asm volatile("cp.async.wait_group %0;" :: "n"(n) : "memory")

#define LDSM4(r0, r1, r2, r3, a) \
    asm volatile("ldmatrix.sync.aligned.m8n8.x4.shared.b16 {%0,%1,%2,%3}, [%4];" \
                 : "=r"(r0), "=r"(r1), "=r"(r2), "=r"(r3) : "r"(a))

#define MMA16816(d, a, b0, b1) \
    asm volatile( \
        "mma.sync.aligned.m16n8k16.row.col.f32.bf16.bf16.f32 " \
        "{%0,%1,%2,%3},{%4,%5,%6,%7},{%8,%9},{%0,%1,%2,%3};" \
        : "+f"((d)[0]), "+f"((d)[1]), "+f"((d)[2]), "+f"((d)[3]) \
        : "r"((a)[0]), "r"((a)[1]), "r"((a)[2]), "r"((a)[3]), \
          "r"(b0), "r"(b1))

// swizzled byte offset of 16B chunk c in row r (row = 64 bytes = 4 chunks)
__device__ __forceinline__ uint32_t swz(int row, int c) {
    return row * 64 + ((c ^ ((row >> 1) & 3)) << 4);
}

// ------------------------------------------------------------- packing -----
__device__ __forceinline__ void split_write(float v, __nv_bfloat16* h,
                                            __nv_bfloat16* l, size_t idx) {
    __nv_bfloat16 hi = __float2bfloat16_rn(v);
    h[idx] = hi;
    l[idx] = __float2bfloat16_rn(v - __bfloat162float(hi));
}

__global__ void pack_w1_kernel(const float* __restrict__ w) {
    int idx = blockIdx.x * blockDim.x + threadIdx.x;
    if (idx >= M1 * K9) return;
    int k = idx % K9, m = idx / K9;
    int kd = m >> 10, co = m & 1023;
    int ci = k / 9,  r  = k % 9;
    split_write(w[co * 27648 + ci * 27 + kd * 9 + r], d_A1h, d_A1l, idx);
}

__global__ void pack_w2_kernel(const float* __restrict__ w) {
    int idx = blockIdx.x * blockDim.x + threadIdx.x;
    if (idx >= M2 * K9) return;
    int k = idx % K9, m = idx / K9;
    int kd = m / 512, co = m % 512;
    int ci = k / 9,  r  = k % 9;
    split_write(w[co * 27648 + ci * 27 + kd * 9 + r], d_A2h, d_A2l, idx);
}

// ------------------------------------------------------------- im2col ------
__global__ void im2col1_kernel(const float* __restrict__ vid) {
    size_t idx = (size_t)blockIdx.x * blockDim.x + threadIdx.x;
    if (idx >= (size_t)N1P * K9) return;
    int k = idx % K9, n = idx / K9;
    float v = 0.0f;
    if (n < N1R) {
        int g  = n / HW, hw = n % HW;
        int y  = hw / 14, x = hw % 14;
        int ci = k / 9,  r = k % 9;
        int kh = r / 3,  kw = r % 3;
        int yy = y + kh - 1, xx = x + kw - 1;
        if (yy >= 0 && yy < 14 && xx >= 0 && xx < 14)
            v = vid[(g * 1024 + ci) * HW + yy * 14 + xx];
    }
    split_write(v, d_B1h, d_B1l, idx);
}

__global__ void im2col2_kernel() {
    size_t idx = (size_t)blockIdx.x * blockDim.x + threadIdx.x;
    if (idx >= (size_t)N2P * K9) return;
    int k = idx % K9, n = idx / K9;
    float v = 0.0f;
    if (n < NSLICE * HW) {
        int s  = n / HW, hw = n % HW;
        int y  = hw / 14, x = hw % 14;
        int ci = k / 9,  r = k % 9;
        int kh = r / 3,  kw = r % 3;
        int yy = y + kh - 1, xx = x + kw - 1;
        if (yy >= 0 && yy < 14 && xx >= 0 && xx < 14)
            v = d_H[(size_t)(s * 1024 + ci) * HW + yy * 14 + xx];
    }
    split_write(v, d_B2h, d_B2l, idx);
}

// --------------------------------------------------------------- GEMM ------
// C(M x Np) = A(M x K) @ B(Np x K)^T, split-bf16 3-pass fused in k-loop.
// 128x128 CTA tile, 8 warps as 4(m) x 2(n) -> warp tile 32x64.
// Stage: Ah | Al | Bh | Bl, each 128 rows x 64 bytes, XOR-swizzled chunks.
#define TILE_B    (128 * 64)                // 8192 bytes per matrix
#define OFF_AH    0
#define OFF_AL    (1 * TILE_B)
#define OFF_BH    (2 * TILE_B)
#define OFF_BL    (3 * TILE_B)
#define STG_B     (4 * TILE_B)              // 32768 bytes per stage
#define SMEM_TOTAL (STAGES * STG_B)         // 98304

__global__ __launch_bounds__(256, 2) void gemm_mma(int which) {
    const __nv_bfloat16* __restrict__ Ah = which ? d_A2h : d_A1h;
    const __nv_bfloat16* __restrict__ Al = which ? d_A2l : d_A1l;
    const __nv_bfloat16* __restrict__ Bh = which ? d_B2h : d_B1h;
    const __nv_bfloat16* __restrict__ Bl = which ? d_B2l : d_B1l;
    float* __restrict__ C = which ? d_C2 : d_F;
    const int Np = which ? N2P : N1P;

    extern __shared__ char smem[];
    const uint32_t smb = smem_u32(smem);
    const int tid  = threadIdx.x;
    const int lane = tid & 31;
    const int wid  = tid >> 5;
    const int wm   = wid >> 1;              // 0..3
    const int wn   = wid & 1;               // 0..1
    const int bym  = blockIdx.y * 128;
    const int bxn  = blockIdx.x * 128;

    const __nv_bfloat16* pAh = Ah + (size_t)bym * K9;
    const __nv_bfloat16* pAl = Al + (size_t)bym * K9;
    const __nv_bfloat16* pBh = Bh + (size_t)bxn * K9;
    const __nv_bfloat16* pBl = Bl + (size_t)bxn * K9;

    // cp.async geometry: 512 16B-chunks per matrix (128 rows x 4); 2/thread.
    int ldRow[2], ldC16[2];
    uint32_t ldDst[2];
#pragma unroll
    for (int t = 0; t < 2; t++) {
        int q = tid + 256 * t;
        ldRow[t] = q >> 2;
        ldC16[t] = q & 3;
        ldDst[t] = swz(ldRow[t], ldC16[t]);
    }

    auto issue_stage = [&](int stage, int k0) {
        uint32_t sb = smb + stage * STG_B;
#pragma unroll
        for (int t = 0; t < 2; t++) {
            size_t so = (size_t)ldRow[t] * K9 + k0 + ldC16[t] * 8;
            CP16(sb + OFF_AH + ldDst[t], pAh + so);
            CP16(sb + OFF_AL + ldDst[t], pAl + so);
            CP16(sb + OFF_BH + ldDst[t], pBh + so);
            CP16(sb + OFF_BL + ldDst[t], pBl + so);
        }
        CPCOMMIT();
    };

    float acc[2][8][4];
#pragma unroll
    for (int mt = 0; mt < 2; mt++)
#pragma unroll
        for (int nt = 0; nt < 8; nt++)
#pragma unroll
            for (int i = 0; i < 4; i++) acc[mt][nt][i] = 0.0f;

    // ldmatrix lane rows + chunk columns
    const int a_row = wm * 32 + (lane & 15);         // + mt*16
    const int a_c   = lane >> 4;                     // 0/1 -> + ks*2
    const int b_row = wn * 64 + ((lane >> 4) & 1) * 8 + (lane & 7);  // + g*16
    const int b_c   = (lane >> 3) & 1;               // 0/1 -> + ks*2

    issue_stage(0, 0);
    issue_stage(1, BK);

    int stage = 0;
    for (int it = 0; it < NCH; it++) {
        if (it + 1 < NCH) { CPWAIT(1); } else { CPWAIT(0); }
        __syncthreads();
        // issue(it+2) targets slot (it-1)%3; barrier proved all readers done
        if (it + 2 < NCH) {
            int ws = stage + 2; if (ws >= STAGES) ws -= STAGES;
            issue_stage(ws, (it + 2) * BK);
        }

        uint32_t sb = smb + stage * STG_B;
#pragma unroll
        for (int ks = 0; ks < 2; ks++) {
            uint32_t ah[2][4], al[2][4];
#pragma unroll
            for (int mt = 0; mt < 2; mt++) {
                uint32_t ao = swz(a_row + mt * 16, ks * 2 + a_c);
                LDSM4(ah[mt][0], ah[mt][1], ah[mt][2], ah[mt][3], sb + OFF_AH + ao);
                LDSM4(al[mt][0], al[mt][1], al[mt][2], al[mt][3], sb + OFF_AL + ao);
            }
#pragma unroll
            for (int g = 0; g < 4; g++) {
                uint32_t bh[4], bl[4];
                uint32_t bo = swz(b_row + g * 16, ks * 2 + b_c);
                LDSM4(bh[0], bh[1], bh[2], bh[3], sb + OFF_BH + bo);
                LDSM4(bl[0], bl[1], bl[2], bl[3], sb + OFF_BL + bo);
#pragma unroll
                for (int mt = 0; mt < 2; mt++) {
                    MMA16816(acc[mt][2 * g],     ah[mt], bh[0], bh[1]);
                    MMA16816(acc[mt][2 * g],     ah[mt], bl[0], bl[1]);
                    MMA16816(acc[mt][2 * g],     al[mt], bh[0], bh[1]);
                    MMA16816(acc[mt][2 * g + 1], ah[mt], bh[2], bh[3]);
                    MMA16816(acc[mt][2 * g + 1], ah[mt], bl[2], bl[3]);
                    MMA16816(acc[mt][2 * g + 1], al[mt], bh[2], bh[3]);
                }
            }
        }
        if (++stage == STAGES) stage = 0;
    }

    // epilogue
#pragma unroll
    for (int mt = 0; mt < 2; mt++) {
        int r0 = bym + wm * 32 + mt * 16 + (lane >> 2);
#pragma unroll
        for (int nt = 0; nt < 8; nt++) {
            int c0 = bxn + wn * 64 + nt * 8 + (lane & 3) * 2;
            *(float2*)(C + (size_t)r0 * Np + c0) =
                make_float2(acc[mt][nt][0], acc[mt][nt][1]);
            *(float2*)(C + (size_t)(r0 + 8) * Np + c0) =
                make_float2(acc[mt][nt][2], acc[mt][nt][3]);
        }
    }
}

// ------------------------------------------------------------- combine -----
__global__ void combine1_kernel(const float* __restrict__ b1) {
    int idx = blockIdx.x * blockDim.x + threadIdx.x;
    if (idx >= NSLICE * 1024 * HW) return;
    int hw = idx % HW;
    int t2 = idx / HW;
    int co = t2 & 1023;
    int s  = t2 >> 10;

    int kd[3] = {-1, -1, -1};
    int gg[3] = {0, 0, 0};
    if (s < 8)       { kd[0] = 1; gg[0] = s - 4;  kd[1] = 2; gg[1] = s - 3; }
    else if (s < 17) { int g = s - 12;
                       kd[0] = 0; gg[0] = g; kd[1] = 1; gg[1] = g + 1;
                       kd[2] = 2; gg[2] = g + 2; }
    else             { int t = s - 17;
                       kd[0] = 0; gg[0] = t - 2; kd[1] = 1; gg[1] = t - 1; }

    float v = b1[co];
#pragma unroll
    for (int e = 0; e < 3; e++) {
        if (kd[e] >= 0 && gg[e] >= 0 && gg[e] < 8)
            v += d_F[(size_t)(kd[e] * 1024 + co) * N1P + gg[e] * HW + hw];
    }
    d_H[idx] = fmaxf(v, 0.0f);
}

// ---------------------------------------------------------------- pool -----
__global__ void pool_kernel(const float* __restrict__ b2) {
    int t  = blockIdx.x >> 9;
    int co = blockIdx.x & 511;
    int s0 = t, s1 = t + 8, s2 = t + 9, s3 = t + 17;
    const float* P0 = d_C2 + (size_t)(0 * 512 + co) * N2P;
    const float* P1 = d_C2 + (size_t)(1 * 512 + co) * N2P;
    const float* P2 = d_C2 + (size_t)(2 * 512 + co) * N2P;

    float m = -1e30f;
    for (int pos = threadIdx.x; pos < 4 * HW; pos += blockDim.x) {
        int d = pos / HW, hw = pos % HW;
        float v;
        if (d == 0)      v = P1[s0 * HW + hw] + P2[s1 * HW + hw];
        else if (d == 1) v = P0[s0 * HW + hw] + P1[s1 * HW + hw] + P2[s2 * HW + hw];
        else if (d == 2) v = P0[s1 * HW + hw] + P1[s2 * HW + hw] + P2[s3 * HW + hw];
        else             v = P0[s2 * HW + hw] + P1[s3 * HW + hw];
        m = fmaxf(m, v);
    }
    __shared__ float red[128];
    red[threadIdx.x] = m;
    __syncthreads();
    for (int sft = 64; sft > 0; sft >>= 1) {
        if (threadIdx.x < sft)
            red[threadIdx.x] = fmaxf(red[threadIdx.x], red[threadIdx.x + sft]);
        __syncthreads();
    }
    if (threadIdx.x == 0)
        d_pool[t * 512 + co] = fmaxf(b2[co] + red[0], 0.0f);
}

// ------------------------------------------------------------------ fc -----
__global__ void fc_kernel(const float* __restrict__ w1, const float* __restrict__ b1,
                          const float* __restrict__ w2, const float* __restrict__ b2,
                          const float* __restrict__ w3, const float* __restrict__ b3,
                          float* __restrict__ out) {
    int t = blockIdx.x;
    int j = threadIdx.x;
    __shared__ float x0[512], x1[512];
    x0[j] = d_pool[t * 512 + j];
    __syncthreads();

    float a = b1[j];
#pragma unroll 8
    for (int i = 0; i < 512; i++) a += x0[i] * w1[j * 512 + i];
    x1[j] = fmaxf(a, 0.0f);
    __syncthreads();

    a = b2[j];
#pragma unroll 8
    for (int i = 0; i < 512; i++) a += x1[i] * w2[j * 512 + i];
    __syncthreads();
    x0[j] = fmaxf(a, 0.0f);
    __syncthreads();

    if (j < 128) {
        a = b3[j];
#pragma unroll 8
        for (int i = 0; i < 512; i++) a += x0[i] * w3[j * 512 + i];
        out[t * 128 + j] = fmaxf(a, 0.0f);
    }
}

// -------------------------------------------------------------- launch -----
extern "C" void kernel_launch(void* const* d_in, const int* in_sizes, int n_in,
                              void* d_out, int out_size) {
    auto find = [&](int sz, int occ) -> const float* {
        int c = 0;
        for (int i = 0; i < n_in; i++)
            if (in_sizes[i] == sz) { if (c == occ) return (const float*)d_in[i]; c++; }
        return nullptr;
    };
    const float* videos = find(1605632, 0);
    const float* w1     = find(28311552, 0);
    const float* b1     = find(1024, 0);
    const float* w2     = find(14155776, 0);
    const float* b2     = find(512, 0);
    const float* l1w    = find(262144, 0);
    const float* l1b    = find(512, 1);
    const float* l2w    = find(262144, 1);
    const float* l2b    = find(512, 2);
    const float* l3w    = find(65536, 0);
    const float* l3b    = find(128, 0);
    float* out = (float*)d_out;

    cudaFuncSetAttribute(gemm_mma, cudaFuncAttributeMaxDynamicSharedMemorySize,
                         SMEM_TOTAL);

    const int TB = 256;
    pack_w1_kernel<<<(M1 * K9 + TB - 1) / TB, TB>>>(w1);
    pack_w2_kernel<<<(M2 * K9 + TB - 1) / TB, TB>>>(w2);
    im2col1_kernel<<<(int)(((size_t)N1P * K9 + TB - 1) / TB), TB>>>(videos);

    gemm_mma<<<dim3(N1P / 128, M1 / 128), 256, SMEM_TOTAL>>>(0);

    combine1_kernel<<<(NSLICE * 1024 * HW + TB - 1) / TB, TB>>>(b1);
    im2col2_kernel<<<(int)(((size_t)N2P * K9 + TB - 1) / TB), TB>>>();

    gemm_mma<<<dim3(N2P / 128, M2 / 128), 256, SMEM_TOTAL>>>(1);

    pool_kernel<<<8 * 512, 128>>>(b2);
    fc_kernel<<<8, 512>>>(l1w, l1b, l2w, l2b, l3w, l3b, out);
}

// round 7
// speedup vs baseline: 3.7761x; 1.5678x over previous
#include <cuda_runtime.h>
#include <cuda_fp16.h>
#include <cstdint>

// ---------------------------------------------------------------------------
// Windowed 3D conv encoder. Per-frame 2D conv decomposition.
// R7: GEMMs = fp16 2-pass (A split hi/lo, pre-scaled x64; B single fp16)
//     on mma.sync/ldmatrix/cp.async. 128x128 CTA tile, 4 stages (96KB),
//     2 CTAs/SM, split-K=3 (reduction folded into combine1/pool).
// ---------------------------------------------------------------------------

#define K9    9216
#define KP    3072          // K per split-K part
#define NKP   3
#define M1    3072
#define N1R   1568
#define N1P   1664          // 13 * 128
#define M2    1536
#define N2P   4992          // 39 * 128
#define NSLICE 25
#define HW    196
#define BK    32
#define NCHP  (KP / BK)     // 96 iters per part
#define STAGES 4
#define ASCALE 64.0f
#define INV_ASCALE 0.015625f

// ------------------------------------------------------------- scratch -----
__device__ __half d_A1h[M1 * K9];
__device__ __half d_A1l[M1 * K9];
__device__ __half d_A2h[M2 * K9];
__device__ __half d_A2l[M2 * K9];
__device__ __half d_B1[N1P * K9];
__device__ __half d_B2[N2P * K9];
__device__ float d_F [NKP * M1 * N1P];
__device__ float d_H [NSLICE * 1024 * HW];
__device__ float d_C2[NKP * M2 * N2P];
__device__ float d_pool[8 * 512];

// ------------------------------------------------------------ PTX bits -----
__device__ __forceinline__ uint32_t smem_u32(const void* p) {
    uint32_t a;
    asm("{ .reg .u64 t; cvta.to.shared.u64 t, %1; cvt.u32.u64 %0, t; }"
        : "=r"(a) : "l"(p));
    return a;
}
#define CP16(dst, src) \
    asm volatile("cp.async.cg.shared.global [%0], [%1], 16;" \
                 :: "r"(dst), "l"(src))
#define CPCOMMIT() asm volatile("cp.async.commit_group;" ::: "memory")
#define CPWAIT(n)  asm volatile("cp.async.wait_group %0;" :: "n"(n) : "memory")

#define LDSM4(r0, r1, r2, r3, a) \
    asm volatile("ldmatrix.sync.aligned.m8n8.x4.shared.b16 {%0,%1,%2,%3}, [%4];" \
                 : "=r"(r0), "=r"(r1), "=r"(r2), "=r"(r3) : "r"(a))

#define MMA16816(d, a, b0, b1) \
    asm volatile( \
        "mma.sync.aligned.m16n8k16.row.col.f32.f16.f16.f32 " \
        "{%0,%1,%2,%3},{%4,%5,%6,%7},{%8,%9},{%0,%1,%2,%3};" \
        : "+f"((d)[0]), "+f"((d)[1]), "+f"((d)[2]), "+f"((d)[3]) \
        : "r"((a)[0]), "r"((a)[1]), "r"((a)[2]), "r"((a)[3]), \
          "r"(b0), "r"(b1))

// swizzled byte offset of 16B chunk c in row r (row = 64 bytes = 4 chunks)
__device__ __forceinline__ uint32_t swz(int row, int c) {
    return row * 64 + ((c ^ ((row >> 1) & 3)) << 4);
}

// ------------------------------------------------------------- packing -----
// A is pre-scaled by ASCALE so lo residuals (~2^-11 * |64w|) stay well above
// fp16's denormal floor; GEMM epilogue multiplies by 1/ASCALE.
__device__ __forceinline__ void split_write_h(float v, __half* h, __half* l,
                                              size_t idx) {
    float s = v * ASCALE;
    __half hi = __float2half_rn(s);
    h[idx] = hi;
    l[idx] = __float2half_rn(s - __half2float(hi));
}

__global__ void pack_w1_kernel(const float* __restrict__ w) {
    int idx = blockIdx.x * blockDim.x + threadIdx.x;
    if (idx >= M1 * K9) return;
    int k = idx % K9, m = idx / K9;
    int kd = m >> 10, co = m & 1023;
    int ci = k / 9,  r  = k % 9;
    split_write_h(w[co * 27648 + ci * 27 + kd * 9 + r], d_A1h, d_A1l, idx);
}

__global__ void pack_w2_kernel(const float* __restrict__ w) {
    int idx = blockIdx.x * blockDim.x + threadIdx.x;
    if (idx >= M2 * K9) return;
    int k = idx % K9, m = idx / K9;
    int kd = m / 512, co = m % 512;
    int ci = k / 9,  r  = k % 9;
    split_write_h(w[co * 27648 + ci * 27 + kd * 9 + r], d_A2h, d_A2l, idx);
}

// ------------------------------------------------------------- im2col ------
__global__ void im2col1_kernel(const float* __restrict__ vid) {
    size_t idx = (size_t)blockIdx.x * blockDim.x + threadIdx.x;
    if (idx >= (size_t)N1P * K9) return;
    int k = idx % K9, n = idx / K9;
    float v = 0.0f;
    if (n < N1R) {
        int g  = n / HW, hw = n % HW;
        int y  = hw / 14, x = hw % 14;
        int ci = k / 9,  r = k % 9;
        int kh = r / 3,  kw = r % 3;
        int yy = y + kh - 1, xx = x + kw - 1;
        if (yy >= 0 && yy < 14 && xx >= 0 && xx < 14)
            v = vid[(g * 1024 + ci) * HW + yy * 14 + xx];
    }
    d_B1[idx] = __float2half_rn(v);
}

__global__ void im2col2_kernel() {
    size_t idx = (size_t)blockIdx.x * blockDim.x + threadIdx.x;
    if (idx >= (size_t)N2P * K9) return;
    int k = idx % K9, n = idx / K9;
    float v = 0.0f;
    if (n < NSLICE * HW) {
        int s  = n / HW, hw = n % HW;
        int y  = hw / 14, x = hw % 14;
        int ci = k / 9,  r = k % 9;
        int kh = r / 3,  kw = r % 3;
        int yy = y + kh - 1, xx = x + kw - 1;
        if (yy >= 0 && yy < 14 && xx >= 0 && xx < 14)
            v = d_H[(size_t)(s * 1024 + ci) * HW + yy * 14 + xx];
    }
    d_B2[idx] = __float2half_rn(v);
}

// --------------------------------------------------------------- GEMM ------
// C_part(M x Np) = A(M, k-slice) @ B(Np, k-slice)^T, fp16 2-pass.
// 128x128 CTA tile, 8 warps as 4(m) x 2(n), warp tile 32x64.
// Stage: Ah | Al | B, each 128 rows x 64 bytes, XOR-swizzled chunks.
// blockIdx.z = split-K part index.
#define TILE_B    (128 * 64)                // 8192 bytes per matrix
#define OFF_AH    0
#define OFF_AL    (1 * TILE_B)
#define OFF_B     (2 * TILE_B)
#define STG_B     (3 * TILE_B)              // 24576 bytes per stage
#define SMEM_TOTAL (STAGES * STG_B)         // 98304

__global__ __launch_bounds__(256, 2) void gemm_mma(int which) {
    const __half* __restrict__ Ah = which ? d_A2h : d_A1h;
    const __half* __restrict__ Al = which ? d_A2l : d_A1l;
    const __half* __restrict__ B  = which ? d_B2  : d_B1;
    float* __restrict__ C = which ? d_C2 : d_F;
    const int Np = which ? N2P : N1P;
    const int Mx = which ? M2  : M1;

    extern __shared__ char smem[];
    const uint32_t smb = smem_u32(smem);
    const int tid  = threadIdx.x;
    const int lane = tid & 31;
    const int wid  = tid >> 5;
    const int wm   = wid >> 1;              // 0..3
    const int wn   = wid & 1;               // 0..1
    const int bym  = blockIdx.y * 128;
    const int bxn  = blockIdx.x * 128;
    const int kprt = blockIdx.z;

    const __half* pAh = Ah + (size_t)bym * K9 + (size_t)kprt * KP;
    const __half* pAl = Al + (size_t)bym * K9 + (size_t)kprt * KP;
    const __half* pB  = B  + (size_t)bxn * K9 + (size_t)kprt * KP;
    float* Cp = C + (size_t)kprt * Mx * Np;

    // cp.async geometry: 512 16B-chunks per matrix (128 rows x 4); 2/thread.
    int ldRow[2], ldC16[2];
    uint32_t ldDst[2];
#pragma unroll
    for (int t = 0; t < 2; t++) {
        int q = tid + 256 * t;
        ldRow[t] = q >> 2;
        ldC16[t] = q & 3;
        ldDst[t] = swz(ldRow[t], ldC16[t]);
    }

    auto issue_stage = [&](int stage, int k0) {
        uint32_t sb = smb + stage * STG_B;
#pragma unroll
        for (int t = 0; t < 2; t++) {
            size_t so = (size_t)ldRow[t] * K9 + k0 + ldC16[t] * 8;
            CP16(sb + OFF_AH + ldDst[t], pAh + so);
            CP16(sb + OFF_AL + ldDst[t], pAl + so);
            CP16(sb + OFF_B  + ldDst[t], pB  + so);
        }
        CPCOMMIT();
    };

    float acc[2][8][4];
#pragma unroll
    for (int mt = 0; mt < 2; mt++)
#pragma unroll
        for (int nt = 0; nt < 8; nt++)
#pragma unroll
            for (int i = 0; i < 4; i++) acc[mt][nt][i] = 0.0f;

    // ldmatrix lane rows + chunk columns
    const int a_row = wm * 32 + (lane & 15);         // + mt*16
    const int a_c   = lane >> 4;                     // 0/1 -> + ks*2
    const int b_row = wn * 64 + ((lane >> 4) & 1) * 8 + (lane & 7);  // + g*16
    const int b_c   = (lane >> 3) & 1;               // 0/1 -> + ks*2

    issue_stage(0, 0);
    issue_stage(1, BK);
    issue_stage(2, 2 * BK);

    int stage = 0;
    for (int it = 0; it < NCHP; it++) {
        // group for stage 'it' is group #it; wait until <=2 pending
        CPWAIT(2);
        __syncthreads();
        // issue(it+3) targets ring slot (it-1)&3; barrier proved readers done
        if (it + 3 < NCHP) {
            int ws = stage + 3; if (ws >= STAGES) ws -= STAGES;
            issue_stage(ws, (it + 3) * BK);
        } else {
            CPCOMMIT();   // keep group counting uniform in the tail
        }

        uint32_t sb = smb + stage * STG_B;
#pragma unroll
        for (int ks = 0; ks < 2; ks++) {
            uint32_t ah[2][4], al[2][4];
#pragma unroll
            for (int mt = 0; mt < 2; mt++) {
                uint32_t ao = swz(a_row + mt * 16, ks * 2 + a_c);
                LDSM4(ah[mt][0], ah[mt][1], ah[mt][2], ah[mt][3], sb + OFF_AH + ao);
                LDSM4(al[mt][0], al[mt][1], al[mt][2], al[mt][3], sb + OFF_AL + ao);
            }
#pragma unroll
            for (int g = 0; g < 4; g++) {
                uint32_t b[4];
                uint32_t bo = swz(b_row + g * 16, ks * 2 + b_c);
                LDSM4(b[0], b[1], b[2], b[3], sb + OFF_B + bo);
#pragma unroll
                for (int mt = 0; mt < 2; mt++) {
                    MMA16816(acc[mt][2 * g],     ah[mt], b[0], b[1]);
                    MMA16816(acc[mt][2 * g],     al[mt], b[0], b[1]);
                    MMA16816(acc[mt][2 * g + 1], ah[mt], b[2], b[3]);
                    MMA16816(acc[mt][2 * g + 1], al[mt], b[2], b[3]);
                }
            }
        }
        if (++stage == STAGES) stage = 0;
    }

    // epilogue (undo A pre-scale)
#pragma unroll
    for (int mt = 0; mt < 2; mt++) {
        int r0 = bym + wm * 32 + mt * 16 + (lane >> 2);
#pragma unroll
        for (int nt = 0; nt < 8; nt++) {
            int c0 = bxn + wn * 64 + nt * 8 + (lane & 3) * 2;
            *(float2*)(Cp + (size_t)r0 * Np + c0) =
                make_float2(acc[mt][nt][0] * INV_ASCALE,
                            acc[mt][nt][1] * INV_ASCALE);
            *(float2*)(Cp + (size_t)(r0 + 8) * Np + c0) =
                make_float2(acc[mt][nt][2] * INV_ASCALE,
                            acc[mt][nt][3] * INV_ASCALE);
        }
    }
}

// ------------------------------------------------------------- combine -----
// Sums split-K parts of F and the window terms, + bias, relu.
__global__ void combine1_kernel(const float* __restrict__ b1) {
    int idx = blockIdx.x * blockDim.x + threadIdx.x;
    if (idx >= NSLICE * 1024 * HW) return;
    int hw = idx % HW;
    int t2 = idx / HW;
    int co = t2 & 1023;
    int s  = t2 >> 10;

    int kd[3] = {-1, -1, -1};
    int gg[3] = {0, 0, 0};
    if (s < 8)       { kd[0] = 1; gg[0] = s - 4;  kd[1] = 2; gg[1] = s - 3; }
    else if (s < 17) { int g = s - 12;
                       kd[0] = 0; gg[0] = g; kd[1] = 1; gg[1] = g + 1;
                       kd[2] = 2; gg[2] = g + 2; }
    else             { int t = s - 17;
                       kd[0] = 0; gg[0] = t - 2; kd[1] = 1; gg[1] = t - 1; }

    float v = b1[co];
#pragma unroll
    for (int e = 0; e < 3; e++) {
        if (kd[e] >= 0 && gg[e] >= 0 && gg[e] < 8) {
            size_t off = (size_t)(kd[e] * 1024 + co) * N1P + gg[e] * HW + hw;
            v += d_F[off] + d_F[(size_t)M1 * N1P + off]
               + d_F[2 * (size_t)M1 * N1P + off];
        }
    }
    d_H[idx] = fmaxf(v, 0.0f);
}

// ---------------------------------------------------------------- pool -----
__device__ __forceinline__ float c2sum(int j, int co, size_t idx) {
    size_t off = (size_t)(j * 512 + co) * N2P + idx;
    return d_C2[off] + d_C2[(size_t)M2 * N2P + off]
         + d_C2[2 * (size_t)M2 * N2P + off];
}

__global__ void pool_kernel(const float* __restrict__ b2) {
    int t  = blockIdx.x >> 9;
    int co = blockIdx.x & 511;
    int s0 = t, s1 = t + 8, s2 = t + 9, s3 = t + 17;

    float m = -1e30f;
    for (int pos = threadIdx.x; pos < 4 * HW; pos += blockDim.x) {
        int d = pos / HW, hw = pos % HW;
        float v;
        if (d == 0)      v = c2sum(1, co, (size_t)s0 * HW + hw)
                           + c2sum(2, co, (size_t)s1 * HW + hw);
        else if (d == 1) v = c2sum(0, co, (size_t)s0 * HW + hw)
                           + c2sum(1, co, (size_t)s1 * HW + hw)
                           + c2sum(2, co, (size_t)s2 * HW + hw);
        else if (d == 2) v = c2sum(0, co, (size_t)s1 * HW + hw)
                           + c2sum(1, co, (size_t)s2 * HW + hw)
                           + c2sum(2, co, (size_t)s3 * HW + hw);
        else             v = c2sum(0, co, (size_t)s2 * HW + hw)
                           + c2sum(1, co, (size_t)s3 * HW + hw);
        m = fmaxf(m, v);
    }
    __shared__ float red[128];
    red[threadIdx.x] = m;
    __syncthreads();
    for (int sft = 64; sft > 0; sft >>= 1) {
        if (threadIdx.x < sft)
            red[threadIdx.x] = fmaxf(red[threadIdx.x], red[threadIdx.x + sft]);
        __syncthreads();
    }
    if (threadIdx.x == 0)
        d_pool[t * 512 + co] = fmaxf(b2[co] + red[0], 0.0f);
}

// ------------------------------------------------------------------ fc -----
__global__ void fc_kernel(const float* __restrict__ w1, const float* __restrict__ b1,
                          const float* __restrict__ w2, const float* __restrict__ b2,
                          const float* __restrict__ w3, const float* __restrict__ b3,
                          float* __restrict__ out) {
    int t = blockIdx.x;
    int j = threadIdx.x;
    __shared__ float x0[512], x1[512];
    x0[j] = d_pool[t * 512 + j];
    __syncthreads();

    float a = b1[j];
#pragma unroll 8
    for (int i = 0; i < 512; i++) a += x0[i] * w1[j * 512 + i];
    x1[j] = fmaxf(a, 0.0f);
    __syncthreads();

    a = b2[j];
#pragma unroll 8
    for (int i = 0; i < 512; i++) a += x1[i] * w2[j * 512 + i];
    __syncthreads();
    x0[j] = fmaxf(a, 0.0f);
    __syncthreads();

    if (j < 128) {
        a = b3[j];
#pragma unroll 8
        for (int i = 0; i < 512; i++) a += x0[i] * w3[j * 512 + i];
        out[t * 128 + j] = fmaxf(a, 0.0f);
    }
}

// -------------------------------------------------------------- launch -----
extern "C" void kernel_launch(void* const* d_in, const int* in_sizes, int n_in,
                              void* d_out, int out_size) {
    auto find = [&](int sz, int occ) -> const float* {
        int c = 0;
        for (int i = 0; i < n_in; i++)
            if (in_sizes[i] == sz) { if (c == occ) return (const float*)d_in[i]; c++; }
        return nullptr;
    };
    const float* videos = find(1605632, 0);
    const float* w1     = find(28311552, 0);
    const float* b1     = find(1024, 0);
    const float* w2     = find(14155776, 0);
    const float* b2     = find(512, 0);
    const float* l1w    = find(262144, 0);
    const float* l1b    = find(512, 1);
    const float* l2w    = find(262144, 1);
    const float* l2b    = find(512, 2);
    const float* l3w    = find(65536, 0);
    const float* l3b    = find(128, 0);
    float* out = (float*)d_out;

    cudaFuncSetAttribute(gemm_mma, cudaFuncAttributeMaxDynamicSharedMemorySize,
                         SMEM_TOTAL);

    const int TB = 256;
    pack_w1_kernel<<<(M1 * K9 + TB - 1) / TB, TB>>>(w1);
    pack_w2_kernel<<<(M2 * K9 + TB - 1) / TB, TB>>>(w2);
    im2col1_kernel<<<(int)(((size_t)N1P * K9 + TB - 1) / TB), TB>>>(videos);

    gemm_mma<<<dim3(N1P / 128, M1 / 128, NKP), 256, SMEM_TOTAL>>>(0);

    combine1_kernel<<<(NSLICE * 1024 * HW + TB - 1) / TB, TB>>>(b1);
    im2col2_kernel<<<(int)(((size_t)N2P * K9 + TB - 1) / TB), TB>>>();

    gemm_mma<<<dim3(N2P / 128, M2 / 128, NKP), 256, SMEM_TOTAL>>>(1);

    pool_kernel<<<8 * 512, 128>>>(b2);
    fc_kernel<<<8, 512>>>(l1w, l1b, l2w, l2b, l3w, l3b, out);
}

// round 8
// speedup vs baseline: 5.1810x; 1.3721x over previous
#include <cuda_runtime.h>
#include <cuda_fp16.h>
#include <cstdint>

// ---------------------------------------------------------------------------
// Windowed 3D conv encoder. Per-frame 2D conv decomposition.
// R8: single-pass fp16 GEMMs (A and B both fp16; fp32 accumulate) on
//     mma.sync/ldmatrix/cp.async. 128x128 CTA tile, 6 stages (96KB),
//     2 CTAs/SM, per-GEMM split-K (4 for GEMM1, 3 for GEMM2) folded into
//     combine1/pool.
// ---------------------------------------------------------------------------

#define K9    9216
#define M1    3072
#define N1R   1568
#define N1P   1664          // 13 * 128
#define M2    1536
#define N2P   4992          // 39 * 128
#define NSLICE 25
#define HW    196
#define BK    32
#define STAGES 6
#define NKP1  4             // split-K parts, GEMM1 (K part = 2304, 72 iters)
#define NKP2  3             // split-K parts, GEMM2 (K part = 3072, 96 iters)

// ------------------------------------------------------------- scratch -----
__device__ __half d_A1[M1 * K9];
__device__ __half d_A2[M2 * K9];
__device__ __half d_B1[N1P * K9];
__device__ __half d_B2[N2P * K9];
__device__ float d_F [NKP1 * M1 * N1P];
__device__ float d_H [NSLICE * 1024 * HW];
__device__ float d_C2[NKP2 * M2 * N2P];
__device__ float d_pool[8 * 512];

// ------------------------------------------------------------ PTX bits -----
__device__ __forceinline__ uint32_t smem_u32(const void* p) {
    uint32_t a;
    asm("{ .reg .u64 t; cvta.to.shared.u64 t, %1; cvt.u32.u64 %0, t; }"
        : "=r"(a) : "l"(p));
    return a;
}
#define CP16(dst, src) \
    asm volatile("cp.async.cg.shared.global [%0], [%1], 16;" \
                 :: "r"(dst), "l"(src))
#define CPCOMMIT() asm volatile("cp.async.commit_group;" ::: "memory")
#define CPWAIT(n)  asm volatile("cp.async.wait_group %0;" :: "n"(n) : "memory")

#define LDSM4(r0, r1, r2, r3, a) \
    asm volatile("ldmatrix.sync.aligned.m8n8.x4.shared.b16 {%0,%1,%2,%3}, [%4];" \
                 : "=r"(r0), "=r"(r1), "=r"(r2), "=r"(r3) : "r"(a))

#define MMA16816(d, a, b0, b1) \
    asm volatile( \
        "mma.sync.aligned.m16n8k16.row.col.f32.f16.f16.f32 " \
        "{%0,%1,%2,%3},{%4,%5,%6,%7},{%8,%9},{%0,%1,%2,%3};" \
        : "+f"((d)[0]), "+f"((d)[1]), "+f"((d)[2]), "+f"((d)[3]) \
        : "r"((a)[0]), "r"((a)[1]), "r"((a)[2]), "r"((a)[3]), \
          "r"(b0), "r"(b1))

// swizzled byte offset of 16B chunk c in row r (row = 64 bytes = 4 chunks)
__device__ __forceinline__ uint32_t swz(int row, int c) {
    return row * 64 + ((c ^ ((row >> 1) & 3)) << 4);
}

// ------------------------------------------------------------- packing -----
__global__ void pack_w1_kernel(const float* __restrict__ w) {
    int idx = blockIdx.x * blockDim.x + threadIdx.x;
    if (idx >= M1 * K9) return;
    int k = idx % K9, m = idx / K9;
    int kd = m >> 10, co = m & 1023;
    int ci = k / 9,  r  = k % 9;
    d_A1[idx] = __float2half_rn(w[co * 27648 + ci * 27 + kd * 9 + r]);
}

__global__ void pack_w2_kernel(const float* __restrict__ w) {
    int idx = blockIdx.x * blockDim.x + threadIdx.x;
    if (idx >= M2 * K9) return;
    int k = idx % K9, m = idx / K9;
    int kd = m / 512, co = m % 512;
    int ci = k / 9,  r  = k % 9;
    d_A2[idx] = __float2half_rn(w[co * 27648 + ci * 27 + kd * 9 + r]);
}

// ------------------------------------------------------------- im2col ------
__global__ void im2col1_kernel(const float* __restrict__ vid) {
    size_t idx = (size_t)blockIdx.x * blockDim.x + threadIdx.x;
    if (idx >= (size_t)N1P * K9) return;
    int k = idx % K9, n = idx / K9;
    float v = 0.0f;
    if (n < N1R) {
        int g  = n / HW, hw = n % HW;
        int y  = hw / 14, x = hw % 14;
        int ci = k / 9,  r = k % 9;
        int kh = r / 3,  kw = r % 3;
        int yy = y + kh - 1, xx = x + kw - 1;
        if (yy >= 0 && yy < 14 && xx >= 0 && xx < 14)
            v = vid[(g * 1024 + ci) * HW + yy * 14 + xx];
    }
    d_B1[idx] = __float2half_rn(v);
}

__global__ void im2col2_kernel() {
    size_t idx = (size_t)blockIdx.x * blockDim.x + threadIdx.x;
    if (idx >= (size_t)N2P * K9) return;
    int k = idx % K9, n = idx / K9;
    float v = 0.0f;
    if (n < NSLICE * HW) {
        int s  = n / HW, hw = n % HW;
        int y  = hw / 14, x = hw % 14;
        int ci = k / 9,  r = k % 9;
        int kh = r / 3,  kw = r % 3;
        int yy = y + kh - 1, xx = x + kw - 1;
        if (yy >= 0 && yy < 14 && xx >= 0 && xx < 14)
            v = d_H[(size_t)(s * 1024 + ci) * HW + yy * 14 + xx];
    }
    d_B2[idx] = __float2half_rn(v);
}

// --------------------------------------------------------------- GEMM ------
// C_part(M x Np) = A(M, k-slice) @ B(Np, k-slice)^T, single-pass fp16.
// 128x128 CTA tile, 8 warps as 4(m) x 2(n), warp tile 32x64.
// Stage: A | B, each 128 rows x 64 bytes, XOR-swizzled chunks.
// blockIdx.z = split-K part (gridDim.z = number of parts).
#define TILE_B    (128 * 64)                // 8192 bytes per matrix
#define OFF_A     0
#define OFF_B     (1 * TILE_B)
#define STG_B     (2 * TILE_B)              // 16384 bytes per stage
#define SMEM_TOTAL (STAGES * STG_B)         // 98304

__global__ __launch_bounds__(256, 2) void gemm_mma(int which) {
    const __half* __restrict__ A = which ? d_A2 : d_A1;
    const __half* __restrict__ B = which ? d_B2 : d_B1;
    float* __restrict__ C = which ? d_C2 : d_F;
    const int Np = which ? N2P : N1P;
    const int Mx = which ? M2  : M1;

    const int nparts = gridDim.z;
    const int KPr    = K9 / nparts;        // k-slice length
    const int iters  = KPr / BK;

    extern __shared__ char smem[];
    const uint32_t smb = smem_u32(smem);
    const int tid  = threadIdx.x;
    const int lane = tid & 31;
    const int wid  = tid >> 5;
    const int wm   = wid >> 1;              // 0..3
    const int wn   = wid & 1;               // 0..1
    const int bym  = blockIdx.y * 128;
    const int bxn  = blockIdx.x * 128;
    const int kprt = blockIdx.z;

    const __half* pA = A + (size_t)bym * K9 + (size_t)kprt * KPr;
    const __half* pB = B + (size_t)bxn * K9 + (size_t)kprt * KPr;
    float* Cp = C + (size_t)kprt * Mx * Np;

    // cp.async geometry: 512 16B-chunks per matrix (128 rows x 4); 2/thread.
    int ldRow[2], ldC16[2];
    uint32_t ldDst[2];
#pragma unroll
    for (int t = 0; t < 2; t++) {
        int q = tid + 256 * t;
        ldRow[t] = q >> 2;
        ldC16[t] = q & 3;
        ldDst[t] = swz(ldRow[t], ldC16[t]);
    }

    auto issue_stage = [&](int stage, int k0) {
        uint32_t sb = smb + stage * STG_B;
#pragma unroll
        for (int t = 0; t < 2; t++) {
            size_t so = (size_t)ldRow[t] * K9 + k0 + ldC16[t] * 8;
            CP16(sb + OFF_A + ldDst[t], pA + so);
            CP16(sb + OFF_B + ldDst[t], pB + so);
        }
        CPCOMMIT();
    };

    float acc[2][8][4];
#pragma unroll
    for (int mt = 0; mt < 2; mt++)
#pragma unroll
        for (int nt = 0; nt < 8; nt++)
#pragma unroll
            for (int i = 0; i < 4; i++) acc[mt][nt][i] = 0.0f;

    // ldmatrix lane rows + chunk columns
    const int a_row = wm * 32 + (lane & 15);         // + mt*16
    const int a_c   = lane >> 4;                     // 0/1 -> + ks*2
    const int b_row = wn * 64 + ((lane >> 4) & 1) * 8 + (lane & 7);  // + g*16
    const int b_c   = (lane >> 3) & 1;               // 0/1 -> + ks*2

#pragma unroll
    for (int s = 0; s < STAGES - 1; s++) issue_stage(s, s * BK);

    int stage = 0;
    for (int it = 0; it < iters; it++) {
        CPWAIT(STAGES - 2);
        __syncthreads();
        // issue(it+STAGES-1) targets ring slot (it-1)%STAGES; the barrier
        // above proved compute(it-1) finished everywhere.
        if (it + STAGES - 1 < iters) {
            int ws = stage + STAGES - 1; if (ws >= STAGES) ws -= STAGES;
            issue_stage(ws, (it + STAGES - 1) * BK);
        } else {
            CPCOMMIT();   // keep group counting uniform in the tail
        }

        uint32_t sb = smb + stage * STG_B;
#pragma unroll
        for (int ks = 0; ks < 2; ks++) {
            uint32_t ah[2][4];
#pragma unroll
            for (int mt = 0; mt < 2; mt++) {
                uint32_t ao = swz(a_row + mt * 16, ks * 2 + a_c);
                LDSM4(ah[mt][0], ah[mt][1], ah[mt][2], ah[mt][3], sb + OFF_A + ao);
            }
#pragma unroll
            for (int g = 0; g < 4; g++) {
                uint32_t b[4];
                uint32_t bo = swz(b_row + g * 16, ks * 2 + b_c);
                LDSM4(b[0], b[1], b[2], b[3], sb + OFF_B + bo);
#pragma unroll
                for (int mt = 0; mt < 2; mt++) {
                    MMA16816(acc[mt][2 * g],     ah[mt], b[0], b[1]);
                    MMA16816(acc[mt][2 * g + 1], ah[mt], b[2], b[3]);
                }
            }
        }
        if (++stage == STAGES) stage = 0;
    }

    // epilogue
#pragma unroll
    for (int mt = 0; mt < 2; mt++) {
        int r0 = bym + wm * 32 + mt * 16 + (lane >> 2);
#pragma unroll
        for (int nt = 0; nt < 8; nt++) {
            int c0 = bxn + wn * 64 + nt * 8 + (lane & 3) * 2;
            *(float2*)(Cp + (size_t)r0 * Np + c0) =
                make_float2(acc[mt][nt][0], acc[mt][nt][1]);
            *(float2*)(Cp + (size_t)(r0 + 8) * Np + c0) =
                make_float2(acc[mt][nt][2], acc[mt][nt][3]);
        }
    }
}

// ------------------------------------------------------------- combine -----
// Sums split-K parts of F and the window terms, + bias, relu.
__global__ void combine1_kernel(const float* __restrict__ b1) {
    int idx = blockIdx.x * blockDim.x + threadIdx.x;
    if (idx >= NSLICE * 1024 * HW) return;
    int hw = idx % HW;
    int t2 = idx / HW;
    int co = t2 & 1023;
    int s  = t2 >> 10;

    int kd[3] = {-1, -1, -1};
    int gg[3] = {0, 0, 0};
    if (s < 8)       { kd[0] = 1; gg[0] = s - 4;  kd[1] = 2; gg[1] = s - 3; }
    else if (s < 17) { int g = s - 12;
                       kd[0] = 0; gg[0] = g; kd[1] = 1; gg[1] = g + 1;
                       kd[2] = 2; gg[2] = g + 2; }
    else             { int t = s - 17;
                       kd[0] = 0; gg[0] = t - 2; kd[1] = 1; gg[1] = t - 1; }

    float v = b1[co];
#pragma unroll
    for (int e = 0; e < 3; e++) {
        if (kd[e] >= 0 && gg[e] >= 0 && gg[e] < 8) {
            size_t off = (size_t)(kd[e] * 1024 + co) * N1P + gg[e] * HW + hw;
#pragma unroll
            for (int p = 0; p < NKP1; p++)
                v += d_F[(size_t)p * M1 * N1P + off];
        }
    }
    d_H[idx] = fmaxf(v, 0.0f);
}

// ---------------------------------------------------------------- pool -----
__device__ __forceinline__ float c2sum(int j, int co, size_t idx) {
    size_t off = (size_t)(j * 512 + co) * N2P + idx;
    float v = 0.0f;
#pragma unroll
    for (int p = 0; p < NKP2; p++)
        v += d_C2[(size_t)p * M2 * N2P + off];
    return v;
}

__global__ void pool_kernel(const float* __restrict__ b2) {
    int t  = blockIdx.x >> 9;
    int co = blockIdx.x & 511;
    int s0 = t, s1 = t + 8, s2 = t + 9, s3 = t + 17;

    float m = -1e30f;
    for (int pos = threadIdx.x; pos < 4 * HW; pos += blockDim.x) {
        int d = pos / HW, hw = pos % HW;
        float v;
        if (d == 0)      v = c2sum(1, co, (size_t)s0 * HW + hw)
                           + c2sum(2, co, (size_t)s1 * HW + hw);
        else if (d == 1) v = c2sum(0, co, (size_t)s0 * HW + hw)
                           + c2sum(1, co, (size_t)s1 * HW + hw)
                           + c2sum(2, co, (size_t)s2 * HW + hw);
        else if (d == 2) v = c2sum(0, co, (size_t)s1 * HW + hw)
                           + c2sum(1, co, (size_t)s2 * HW + hw)
                           + c2sum(2, co, (size_t)s3 * HW + hw);
        else             v = c2sum(0, co, (size_t)s2 * HW + hw)
                           + c2sum(1, co, (size_t)s3 * HW + hw);
        m = fmaxf(m, v);
    }
    __shared__ float red[128];
    red[threadIdx.x] = m;
    __syncthreads();
    for (int sft = 64; sft > 0; sft >>= 1) {
        if (threadIdx.x < sft)
            red[threadIdx.x] = fmaxf(red[threadIdx.x], red[threadIdx.x + sft]);
        __syncthreads();
    }
    if (threadIdx.x == 0)
        d_pool[t * 512 + co] = fmaxf(b2[co] + red[0], 0.0f);
}

// ------------------------------------------------------------------ fc -----
__global__ void fc_kernel(const float* __restrict__ w1, const float* __restrict__ b1,
                          const float* __restrict__ w2, const float* __restrict__ b2,
                          const float* __restrict__ w3, const float* __restrict__ b3,
                          float* __restrict__ out) {
    int t = blockIdx.x;
    int j = threadIdx.x;
    __shared__ float x0[512], x1[512];
    x0[j] = d_pool[t * 512 + j];
    __syncthreads();

    float a = b1[j];
#pragma unroll 8
    for (int i = 0; i < 512; i++) a += x0[i] * w1[j * 512 + i];
    x1[j] = fmaxf(a, 0.0f);
    __syncthreads();

    a = b2[j];
#pragma unroll 8
    for (int i = 0; i < 512; i++) a += x1[i] * w2[j * 512 + i];
    __syncthreads();
    x0[j] = fmaxf(a, 0.0f);
    __syncthreads();

    if (j < 128) {
        a = b3[j];
#pragma unroll 8
        for (int i = 0; i < 512; i++) a += x0[i] * w3[j * 512 + i];
        out[t * 128 + j] = fmaxf(a, 0.0f);
    }
}

// -------------------------------------------------------------- launch -----
extern "C" void kernel_launch(void* const* d_in, const int* in_sizes, int n_in,
                              void* d_out, int out_size) {
    auto find = [&](int sz, int occ) -> const float* {
        int c = 0;
        for (int i = 0; i < n_in; i++)
            if (in_sizes[i] == sz) { if (c == occ) return (const float*)d_in[i]; c++; }
        return nullptr;
    };
    const float* videos = find(1605632, 0);
    const float* w1     = find(28311552, 0);
    const float* b1     = find(1024, 0);
    const float* w2     = find(14155776, 0);
    const float* b2     = find(512, 0);
    const float* l1w    = find(262144, 0);
    const float* l1b    = find(512, 1);
    const float* l2w    = find(262144, 1);
    const float* l2b    = find(512, 2);
    const float* l3w    = find(65536, 0);
    const float* l3b    = find(128, 0);
    float* out = (float*)d_out;

    cudaFuncSetAttribute(gemm_mma, cudaFuncAttributeMaxDynamicSharedMemorySize,
                         SMEM_TOTAL);

    const int TB = 256;
    pack_w1_kernel<<<(M1 * K9 + TB - 1) / TB, TB>>>(w1);
    pack_w2_kernel<<<(M2 * K9 + TB - 1) / TB, TB>>>(w2);
    im2col1_kernel<<<(int)(((size_t)N1P * K9 + TB - 1) / TB), TB>>>(videos);

    gemm_mma<<<dim3(N1P / 128, M1 / 128, NKP1), 256, SMEM_TOTAL>>>(0);

    combine1_kernel<<<(NSLICE * 1024 * HW + TB - 1) / TB, TB>>>(b1);
    im2col2_kernel<<<(int)(((size_t)N2P * K9 + TB - 1) / TB), TB>>>();

    gemm_mma<<<dim3(N2P / 128, M2 / 128, NKP2), 256, SMEM_TOTAL>>>(1);

    pool_kernel<<<8 * 512, 128>>>(b2);
    fc_kernel<<<8, 512>>>(l1w, l1b, l2w, l2b, l3w, l3b, out);
}

// round 9
// speedup vs baseline: 5.6836x; 1.0970x over previous
#include <cuda_runtime.h>
#include <cuda_fp16.h>
#include <cstdint>

// ---------------------------------------------------------------------------
// Windowed 3D conv encoder. Per-frame 2D conv decomposition.
// R9: single-pass fp16 GEMMs. GEMM1 computes F^T (operands swapped) so
//     combine1 reads/writes contiguously and emits fp16 H directly.
//     GEMM2 uses K ordering k = r*1024+ci so im2col2 is a uint4 block copy.
//     128x128 CTA tile, 6 stages, 2 CTAs/SM, split-K folded into combine/pool.
// ---------------------------------------------------------------------------

#define K9    9216
#define M1    3072
#define N1R   1568
#define N1P   1664          // 13 * 128
#define M2    1536
#define N2R   4900
#define N2P   4992          // 39 * 128
#define NSLICE 25
#define HW    196
#define BK    32
#define STAGES 6
#define NKP1  4             // split-K parts, GEMM1
#define NKP2  3             // split-K parts, GEMM2

// ------------------------------------------------------------- scratch -----
__device__ __half d_A1[M1 * K9];
__device__ __half d_A2[M2 * K9];
__device__ __half d_B1[N1P * K9];
__device__ __half d_B2[N2P * K9];
__device__ float  d_F [NKP1 * N1P * M1];      // F^T: [part][n][m]
__device__ __half d_Ht[NSLICE * HW * 1024];   // H transposed: [pixel][ci] fp16
__device__ float  d_C2[NKP2 * M2 * N2P];
__device__ float  d_pool[8 * 512];

// ------------------------------------------------------------ PTX bits -----
__device__ __forceinline__ uint32_t smem_u32(const void* p) {
    uint32_t a;
    asm("{ .reg .u64 t; cvta.to.shared.u64 t, %1; cvt.u32.u64 %0, t; }"
        : "=r"(a) : "l"(p));
    return a;
}
#define CP16(dst, src) \
    asm volatile("cp.async.cg.shared.global [%0], [%1], 16;" \
                 :: "r"(dst), "l"(src))
#define CPCOMMIT() asm volatile("cp.async.commit_group;" ::: "memory")
#define CPWAIT(n)  asm volatile("cp.async.wait_group %0;" :: "n"(n) : "memory")

#define LDSM4(r0, r1, r2, r3, a) \
    asm volatile("ldmatrix.sync.aligned.m8n8.x4.shared.b16 {%0,%1,%2,%3}, [%4];" \
                 : "=r"(r0), "=r"(r1), "=r"(r2), "=r"(r3) : "r"(a))

#define MMA16816(d, a, b0, b1) \
    asm volatile( \
        "mma.sync.aligned.m16n8k16.row.col.f32.f16.f16.f32 " \
        "{%0,%1,%2,%3},{%4,%5,%6,%7},{%8,%9},{%0,%1,%2,%3};" \
        : "+f"((d)[0]), "+f"((d)[1]), "+f"((d)[2]), "+f"((d)[3]) \
        : "r"((a)[0]), "r"((a)[1]), "r"((a)[2]), "r"((a)[3]), \
          "r"(b0), "r"(b1))

// swizzled byte offset of 16B chunk c in row r (row = 64 bytes = 4 chunks)
__device__ __forceinline__ uint32_t swz(int row, int c) {
    return row * 64 + ((c ^ ((row >> 1) & 3)) << 4);
}

// ------------------------------------------------------------- packing -----
// A1: [m = kd*1024+co][k = ci*9+r]  (must match B1's k ordering)
__global__ void pack_w1_kernel(const float* __restrict__ w) {
    int idx = blockIdx.x * blockDim.x + threadIdx.x;
    if (idx >= M1 * K9) return;
    int k = idx % K9, m = idx / K9;
    int kd = m >> 10, co = m & 1023;
    int ci = k / 9,  r  = k % 9;
    d_A1[idx] = __float2half_rn(w[co * 27648 + ci * 27 + kd * 9 + r]);
}

// A2: [m = kd*512+co][k = r*1024+ci]  (must match B2's k ordering)
__global__ void pack_w2_kernel(const float* __restrict__ w) {
    int idx = blockIdx.x * blockDim.x + threadIdx.x;
    if (idx >= M2 * K9) return;
    int k = idx % K9, m = idx / K9;
    int r = k >> 10,  ci = k & 1023;
    int kd = m / 512, co = m % 512;
    d_A2[idx] = __float2half_rn(w[co * 27648 + ci * 27 + kd * 9 + r]);
}

// ------------------------------------------------------------- im2col ------
__global__ void im2col1_kernel(const float* __restrict__ vid) {
    size_t idx = (size_t)blockIdx.x * blockDim.x + threadIdx.x;
    if (idx >= (size_t)N1P * K9) return;
    int k = idx % K9, n = idx / K9;
    float v = 0.0f;
    if (n < N1R) {
        int g  = n / HW, hw = n % HW;
        int y  = hw / 14, x = hw % 14;
        int ci = k / 9,  r = k % 9;
        int kh = r / 3,  kw = r % 3;
        int yy = y + kh - 1, xx = x + kw - 1;
        if (yy >= 0 && yy < 14 && xx >= 0 && xx < 14)
            v = vid[(g * 1024 + ci) * HW + yy * 14 + xx];
    }
    d_B1[idx] = __float2half_rn(v);
}

// B2[n][r*1024 + ci] = Ht[(s, shifted pixel)][ci] : pure 16B block copy.
__global__ void im2col2_kernel() {
    int idx = blockIdx.x * blockDim.x + threadIdx.x;
    if (idx >= N2P * 9 * 128) return;
    int ci8 = idx & 127;            // 8-element fp16 block
    int t   = idx >> 7;
    int r   = t % 9;
    int n   = t / 9;
    uint4 val = make_uint4(0, 0, 0, 0);
    if (n < N2R) {
        int s  = n / HW, hw = n % HW;
        int y  = hw / 14, x = hw % 14;
        int kh = r / 3,  kw = r % 3;
        int yy = y + kh - 1, xx = x + kw - 1;
        if (yy >= 0 && yy < 14 && xx >= 0 && xx < 14)
            val = *(const uint4*)&d_Ht[((size_t)s * HW + yy * 14 + xx) * 1024
                                       + ci8 * 8];
    }
    *(uint4*)&d_B2[(size_t)n * K9 + r * 1024 + ci8 * 8] = val;
}

// --------------------------------------------------------------- GEMM ------
// C(rows x Ncols) = A(rows, k-slice) @ B(Ncols, k-slice)^T, fp16, fp32 acc.
// Both operands are [row][K9] K-major; blockIdx.z = split-K part.
#define TILE_B    (128 * 64)
#define OFF_A     0
#define OFF_B     (1 * TILE_B)
#define STG_B     (2 * TILE_B)
#define SMEM_TOTAL (STAGES * STG_B)         // 98304

__global__ __launch_bounds__(256, 2) void gemm_mma(
    const __half* __restrict__ A, const __half* __restrict__ B,
    float* __restrict__ C, int Ncols) {
    const int nparts = gridDim.z;
    const int KPr    = K9 / nparts;
    const int iters  = KPr / BK;
    const int rowsT  = gridDim.y * 128;

    extern __shared__ char smem[];
    const uint32_t smb = smem_u32(smem);
    const int tid  = threadIdx.x;
    const int lane = tid & 31;
    const int wid  = tid >> 5;
    const int wm   = wid >> 1;              // 0..3
    const int wn   = wid & 1;               // 0..1
    const int bym  = blockIdx.y * 128;      // output rows
    const int bxn  = blockIdx.x * 128;      // output cols
    const int kprt = blockIdx.z;

    const __half* pA = A + (size_t)bym * K9 + (size_t)kprt * KPr;
    const __half* pB = B + (size_t)bxn * K9 + (size_t)kprt * KPr;
    float* Cp = C + (size_t)kprt * rowsT * Ncols;

    int ldRow[2], ldC16[2];
    uint32_t ldDst[2];
#pragma unroll
    for (int t = 0; t < 2; t++) {
        int q = tid + 256 * t;
        ldRow[t] = q >> 2;
        ldC16[t] = q & 3;
        ldDst[t] = swz(ldRow[t], ldC16[t]);
    }

    auto issue_stage = [&](int stage, int k0) {
        uint32_t sb = smb + stage * STG_B;
#pragma unroll
        for (int t = 0; t < 2; t++) {
            size_t so = (size_t)ldRow[t] * K9 + k0 + ldC16[t] * 8;
            CP16(sb + OFF_A + ldDst[t], pA + so);
            CP16(sb + OFF_B + ldDst[t], pB + so);
        }
        CPCOMMIT();
    };

    float acc[2][8][4];
#pragma unroll
    for (int mt = 0; mt < 2; mt++)
#pragma unroll
        for (int nt = 0; nt < 8; nt++)
#pragma unroll
            for (int i = 0; i < 4; i++) acc[mt][nt][i] = 0.0f;

    const int a_row = wm * 32 + (lane & 15);
    const int a_c   = lane >> 4;
    const int b_row = wn * 64 + ((lane >> 4) & 1) * 8 + (lane & 7);
    const int b_c   = (lane >> 3) & 1;

#pragma unroll
    for (int s = 0; s < STAGES - 1; s++) issue_stage(s, s * BK);

    int stage = 0;
    for (int it = 0; it < iters; it++) {
        CPWAIT(STAGES - 2);
        __syncthreads();
        if (it + STAGES - 1 < iters) {
            int ws = stage + STAGES - 1; if (ws >= STAGES) ws -= STAGES;
            issue_stage(ws, (it + STAGES - 1) * BK);
        } else {
            CPCOMMIT();
        }

        uint32_t sb = smb + stage * STG_B;
#pragma unroll
        for (int ks = 0; ks < 2; ks++) {
            uint32_t ah[2][4];
#pragma unroll
            for (int mt = 0; mt < 2; mt++) {
                uint32_t ao = swz(a_row + mt * 16, ks * 2 + a_c);
                LDSM4(ah[mt][0], ah[mt][1], ah[mt][2], ah[mt][3], sb + OFF_A + ao);
            }
#pragma unroll
            for (int g = 0; g < 4; g++) {
                uint32_t b[4];
                uint32_t bo = swz(b_row + g * 16, ks * 2 + b_c);
                LDSM4(b[0], b[1], b[2], b[3], sb + OFF_B + bo);
#pragma unroll
                for (int mt = 0; mt < 2; mt++) {
                    MMA16816(acc[mt][2 * g],     ah[mt], b[0], b[1]);
                    MMA16816(acc[mt][2 * g + 1], ah[mt], b[2], b[3]);
                }
            }
        }
        if (++stage == STAGES) stage = 0;
    }

#pragma unroll
    for (int mt = 0; mt < 2; mt++) {
        int r0 = bym + wm * 32 + mt * 16 + (lane >> 2);
#pragma unroll
        for (int nt = 0; nt < 8; nt++) {
            int c0 = bxn + wn * 64 + nt * 8 + (lane & 3) * 2;
            *(float2*)(Cp + (size_t)r0 * Ncols + c0) =
                make_float2(acc[mt][nt][0], acc[mt][nt][1]);
            *(float2*)(Cp + (size_t)(r0 + 8) * Ncols + c0) =
                make_float2(acc[mt][nt][2], acc[mt][nt][3]);
        }
    }
}

// ------------------------------------------------------------- combine -----
// Ht[(s,hw)][co] = relu(b1[co] + sum_e sum_p F^T[p][n_e][kd_e*1024+co]).
// One thread = 4 consecutive co (float4 reads, 8B fp16 write).
__global__ void combine1_kernel(const float* __restrict__ b1) {
    int idx = blockIdx.x * blockDim.x + threadIdx.x;
    if (idx >= NSLICE * HW * 256) return;
    int co4 = (idx & 255) << 2;
    int pix = idx >> 8;          // s*HW + hw
    int hw  = pix % HW;
    int s   = pix / HW;

    int kd[3] = {-1, -1, -1};
    int gg[3] = {0, 0, 0};
    if (s < 8)       { kd[0] = 1; gg[0] = s - 4;  kd[1] = 2; gg[1] = s - 3; }
    else if (s < 17) { int g = s - 12;
                       kd[0] = 0; gg[0] = g; kd[1] = 1; gg[1] = g + 1;
                       kd[2] = 2; gg[2] = g + 2; }
    else             { int t = s - 17;
                       kd[0] = 0; gg[0] = t - 2; kd[1] = 1; gg[1] = t - 1; }

    float4 v = *(const float4*)(b1 + co4);
#pragma unroll
    for (int e = 0; e < 3; e++) {
        if (kd[e] >= 0 && gg[e] >= 0 && gg[e] < 8) {
            size_t off = ((size_t)gg[e] * HW + hw) * M1 + (kd[e] << 10) + co4;
#pragma unroll
            for (int p = 0; p < NKP1; p++) {
                float4 f = *(const float4*)(d_F + (size_t)p * N1P * M1 + off);
                v.x += f.x; v.y += f.y; v.z += f.z; v.w += f.w;
            }
        }
    }
    __half2 h0 = __floats2half2_rn(fmaxf(v.x, 0.0f), fmaxf(v.y, 0.0f));
    __half2 h1 = __floats2half2_rn(fmaxf(v.z, 0.0f), fmaxf(v.w, 0.0f));
    uint2 pk;
    pk.x = *(uint32_t*)&h0;
    pk.y = *(uint32_t*)&h1;
    *(uint2*)&d_Ht[(size_t)pix * 1024 + co4] = pk;
}

// ---------------------------------------------------------------- pool -----
__device__ __forceinline__ float c2sum(int j, int co, size_t idx) {
    size_t off = (size_t)(j * 512 + co) * N2P + idx;
    float v = 0.0f;
#pragma unroll
    for (int p = 0; p < NKP2; p++)
        v += d_C2[(size_t)p * M2 * N2P + off];
    return v;
}

__global__ void pool_kernel(const float* __restrict__ b2) {
    int t  = blockIdx.x >> 9;
    int co = blockIdx.x & 511;
    int s0 = t, s1 = t + 8, s2 = t + 9, s3 = t + 17;

    float m = -1e30f;
    for (int pos = threadIdx.x; pos < 4 * HW; pos += blockDim.x) {
        int d = pos / HW, hw = pos % HW;
        float v;
        if (d == 0)      v = c2sum(1, co, (size_t)s0 * HW + hw)
                           + c2sum(2, co, (size_t)s1 * HW + hw);
        else if (d == 1) v = c2sum(0, co, (size_t)s0 * HW + hw)
                           + c2sum(1, co, (size_t)s1 * HW + hw)
                           + c2sum(2, co, (size_t)s2 * HW + hw);
        else if (d == 2) v = c2sum(0, co, (size_t)s1 * HW + hw)
                           + c2sum(1, co, (size_t)s2 * HW + hw)
                           + c2sum(2, co, (size_t)s3 * HW + hw);
        else             v = c2sum(0, co, (size_t)s2 * HW + hw)
                           + c2sum(1, co, (size_t)s3 * HW + hw);
        m = fmaxf(m, v);
    }
    __shared__ float red[128];
    red[threadIdx.x] = m;
    __syncthreads();
    for (int sft = 64; sft > 0; sft >>= 1) {
        if (threadIdx.x < sft)
            red[threadIdx.x] = fmaxf(red[threadIdx.x], red[threadIdx.x + sft]);
        __syncthreads();
    }
    if (threadIdx.x == 0)
        d_pool[t * 512 + co] = fmaxf(b2[co] + red[0], 0.0f);
}

// ------------------------------------------------------------------ fc -----
__global__ void fc_kernel(const float* __restrict__ w1, const float* __restrict__ b1,
                          const float* __restrict__ w2, const float* __restrict__ b2,
                          const float* __restrict__ w3, const float* __restrict__ b3,
                          float* __restrict__ out) {
    int t = blockIdx.x;
    int j = threadIdx.x;
    __shared__ float x0[512], x1[512];
    x0[j] = d_pool[t * 512 + j];
    __syncthreads();

    float a = b1[j];
#pragma unroll 8
    for (int i = 0; i < 512; i++) a += x0[i] * w1[j * 512 + i];
    x1[j] = fmaxf(a, 0.0f);
    __syncthreads();

    a = b2[j];
#pragma unroll 8
    for (int i = 0; i < 512; i++) a += x1[i] * w2[j * 512 + i];
    __syncthreads();
    x0[j] = fmaxf(a, 0.0f);
    __syncthreads();

    if (j < 128) {
        a = b3[j];
#pragma unroll 8
        for (int i = 0; i < 512; i++) a += x0[i] * w3[j * 512 + i];
        out[t * 128 + j] = fmaxf(a, 0.0f);
    }
}

// -------------------------------------------------------------- launch -----
extern "C" void kernel_launch(void* const* d_in, const int* in_sizes, int n_in,
                              void* d_out, int out_size) {
    auto find = [&](int sz, int occ) -> const float* {
        int c = 0;
        for (int i = 0; i < n_in; i++)
            if (in_sizes[i] == sz) { if (c == occ) return (const float*)d_in[i]; c++; }
        return nullptr;
    };
    const float* videos = find(1605632, 0);
    const float* w1     = find(28311552, 0);
    const float* b1     = find(1024, 0);
    const float* w2     = find(14155776, 0);
    const float* b2     = find(512, 0);
    const float* l1w    = find(262144, 0);
    const float* l1b    = find(512, 1);
    const float* l2w    = find(262144, 1);
    const float* l2b    = find(512, 2);
    const float* l3w    = find(65536, 0);
    const float* l3b    = find(128, 0);
    float* out = (float*)d_out;

    cudaFuncSetAttribute(gemm_mma, cudaFuncAttributeMaxDynamicSharedMemorySize,
                         SMEM_TOTAL);

    const int TB = 256;
    __half *A1p, *A2p, *B1p, *B2p;
    float *Fp, *C2p;
    cudaGetSymbolAddress((void**)&A1p, d_A1);
    cudaGetSymbolAddress((void**)&A2p, d_A2);
    cudaGetSymbolAddress((void**)&B1p, d_B1);
    cudaGetSymbolAddress((void**)&B2p, d_B2);
    cudaGetSymbolAddress((void**)&Fp,  d_F);
    cudaGetSymbolAddress((void**)&C2p, d_C2);

    pack_w1_kernel<<<(M1 * K9 + TB - 1) / TB, TB>>>(w1);
    pack_w2_kernel<<<(M2 * K9 + TB - 1) / TB, TB>>>(w2);
    im2col1_kernel<<<(int)(((size_t)N1P * K9 + TB - 1) / TB), TB>>>(videos);

    // F^T = B1 @ A1^T : rows = pixels (N1P), cols = M1
    gemm_mma<<<dim3(M1 / 128, N1P / 128, NKP1), 256, SMEM_TOTAL>>>(
        B1p, A1p, Fp, M1);

    combine1_kernel<<<(NSLICE * HW * 256 + TB - 1) / TB, TB>>>(b1);
    im2col2_kernel<<<(N2P * 9 * 128 + TB - 1) / TB, TB>>>();

    // C2 = A2 @ B2^T : rows = M2, cols = N2P
    gemm_mma<<<dim3(N2P / 128, M2 / 128, NKP2), 256, SMEM_TOTAL>>>(
        A2p, B2p, C2p, N2P);

    pool_kernel<<<8 * 512, 128>>>(b2);
    fc_kernel<<<8, 512>>>(l1w, l1b, l2w, l2b, l3w, l3b, out);
}

// round 10
// speedup vs baseline: 7.0427x; 1.2391x over previous
#include <cuda_runtime.h>
#include <cuda_fp16.h>
#include <cstdint>

// ---------------------------------------------------------------------------
// Windowed 3D conv encoder. Per-frame 2D conv decomposition.
// R10: 4-warp 128x128 CTA tile (warp 64x64) -> smem traffic 187B/HMMA,
//      tensor-bound. Unified K ordering k = r*1024+ci for both GEMMs:
//      video pre-transposed -> both im2cols are uint4 block copies, both
//      weight packs fully coalesced. 6 stages, 2 CTAs/SM, split-K 4/3.
// ---------------------------------------------------------------------------

#define K9    9216
#define M1    3072
#define N1R   1568
#define N1P   1664          // 13 * 128
#define M2    1536
#define N2R   4900
#define N2P   4992          // 39 * 128
#define NSLICE 25
#define HW    196
#define BK    32
#define STAGES 6
#define NKP1  4
#define NKP2  3

// ------------------------------------------------------------- scratch -----
__device__ __half d_Vt[8 * HW * 1024];        // video^T: [g*HW+hw][ci] fp16
__device__ __half d_A1[M1 * K9];
__device__ __half d_A2[M2 * K9];
__device__ __half d_B1[N1P * K9];
__device__ __half d_B2[N2P * K9];
__device__ float  d_F [NKP1 * N1P * M1];      // F^T: [part][n][m]
__device__ __half d_Ht[NSLICE * HW * 1024];   // H^T: [pixel][co] fp16
__device__ float  d_C2[NKP2 * M2 * N2P];
__device__ float  d_pool[8 * 512];

// ------------------------------------------------------------ PTX bits -----
__device__ __forceinline__ uint32_t smem_u32(const void* p) {
    uint32_t a;
    asm("{ .reg .u64 t; cvta.to.shared.u64 t, %1; cvt.u32.u64 %0, t; }"
        : "=r"(a) : "l"(p));
    return a;
}
#define CP16(dst, src) \
    asm volatile("cp.async.cg.shared.global [%0], [%1], 16;" \
                 :: "r"(dst), "l"(src))
#define CPCOMMIT() asm volatile("cp.async.commit_group;" ::: "memory")
#define CPWAIT(n)  asm volatile("cp.async.wait_group %0;" :: "n"(n) : "memory")

#define LDSM4(r0, r1, r2, r3, a) \
    asm volatile("ldmatrix.sync.aligned.m8n8.x4.shared.b16 {%0,%1,%2,%3}, [%4];" \
                 : "=r"(r0), "=r"(r1), "=r"(r2), "=r"(r3) : "r"(a))

#define MMA16816(d, a, b0, b1) \
    asm volatile( \
        "mma.sync.aligned.m16n8k16.row.col.f32.f16.f16.f32 " \
        "{%0,%1,%2,%3},{%4,%5,%6,%7},{%8,%9},{%0,%1,%2,%3};" \
        : "+f"((d)[0]), "+f"((d)[1]), "+f"((d)[2]), "+f"((d)[3]) \
        : "r"((a)[0]), "r"((a)[1]), "r"((a)[2]), "r"((a)[3]), \
          "r"(b0), "r"(b1))

// swizzled byte offset of 16B chunk c in row r (row = 64 bytes = 4 chunks)
__device__ __forceinline__ uint32_t swz(int row, int c) {
    return row * 64 + ((c ^ ((row >> 1) & 3)) << 4);
}

// ---------------------------------------------------- video transpose ------
// vid[g][ci][hw] f32 -> Vt[g*HW+hw][ci] fp16, tiled via smem.
__global__ void transpose_video_kernel(const float* __restrict__ vid) {
    __shared__ float tile[32][33];
    int g   = blockIdx.x;
    int hw0 = blockIdx.y * 32;
    int ci0 = blockIdx.z * 32;
    int tx = threadIdx.x, ty = threadIdx.y;   // 32 x 8
#pragma unroll
    for (int j = 0; j < 4; j++) {
        int ci = ci0 + ty + 8 * j, hw = hw0 + tx;
        tile[ty + 8 * j][tx] =
            (hw < HW) ? vid[((size_t)g * 1024 + ci) * HW + hw] : 0.0f;
    }
    __syncthreads();
#pragma unroll
    for (int j = 0; j < 4; j++) {
        int hw = hw0 + ty + 8 * j, ci = ci0 + tx;
        if (hw < HW)
            d_Vt[((size_t)g * HW + hw) * 1024 + ci] =
                __float2half_rn(tile[tx][ty + 8 * j]);
    }
}

// ------------------------------------------------------------- packing -----
// thread = (co, ci): 27 contiguous f32 reads; coalesced fp16 writes.
// A1[m = kd*1024+co][k = r*1024+ci]
__global__ void pack_w1_kernel(const float* __restrict__ w) {
    int idx = blockIdx.x * blockDim.x + threadIdx.x;
    if (idx >= 1024 * 1024) return;
    int ci = idx & 1023, co = idx >> 10;
    const float* src = w + (size_t)co * 27648 + ci * 27;
    float v[27];
#pragma unroll
    for (int i = 0; i < 27; i++) v[i] = src[i];
#pragma unroll
    for (int kd = 0; kd < 3; kd++)
#pragma unroll
        for (int r = 0; r < 9; r++)
            d_A1[(size_t)((kd << 10) + co) * K9 + (r << 10) + ci] =
                __float2half_rn(v[kd * 9 + r]);
}

// A2[m = kd*512+co][k = r*1024+ci]
__global__ void pack_w2_kernel(const float* __restrict__ w) {
    int idx = blockIdx.x * blockDim.x + threadIdx.x;
    if (idx >= 512 * 1024) return;
    int ci = idx & 1023, co = idx >> 10;
    const float* src = w + (size_t)co * 27648 + ci * 27;
    float v[27];
#pragma unroll
    for (int i = 0; i < 27; i++) v[i] = src[i];
#pragma unroll
    for (int kd = 0; kd < 3; kd++)
#pragma unroll
        for (int r = 0; r < 9; r++)
            d_A2[(size_t)(kd * 512 + co) * K9 + (r << 10) + ci] =
                __float2half_rn(v[kd * 9 + r]);
}

// ------------------------------------------------------------- im2col ------
// B1[n = g*HW+hw][k = r*1024+ci] = Vt[(g, shifted pixel)][ci] : 16B copies.
__global__ void im2col1_kernel() {
    int idx = blockIdx.x * blockDim.x + threadIdx.x;
    if (idx >= N1P * 9 * 128) return;
    int ci8 = idx & 127;
    int t   = idx >> 7;
    int r   = t % 9;
    int n   = t / 9;
    uint4 val = make_uint4(0, 0, 0, 0);
    if (n < N1R) {
        int g  = n / HW, hw = n % HW;
        int y  = hw / 14, x = hw % 14;
        int kh = r / 3,  kw = r % 3;
        int yy = y + kh - 1, xx = x + kw - 1;
        if (yy >= 0 && yy < 14 && xx >= 0 && xx < 14)
            val = *(const uint4*)&d_Vt[((size_t)g * HW + yy * 14 + xx) * 1024
                                       + ci8 * 8];
    }
    *(uint4*)&d_B1[(size_t)n * K9 + (r << 10) + ci8 * 8] = val;
}

// B2[n][k = r*1024+ci] = Ht[(s, shifted pixel)][ci] : 16B copies.
__global__ void im2col2_kernel() {
    int idx = blockIdx.x * blockDim.x + threadIdx.x;
    if (idx >= N2P * 9 * 128) return;
    int ci8 = idx & 127;
    int t   = idx >> 7;
    int r   = t % 9;
    int n   = t / 9;
    uint4 val = make_uint4(0, 0, 0, 0);
    if (n < N2R) {
        int s  = n / HW, hw = n % HW;
        int y  = hw / 14, x = hw % 14;
        int kh = r / 3,  kw = r % 3;
        int yy = y + kh - 1, xx = x + kw - 1;
        if (yy >= 0 && yy < 14 && xx >= 0 && xx < 14)
            val = *(const uint4*)&d_Ht[((size_t)s * HW + yy * 14 + xx) * 1024
                                       + ci8 * 8];
    }
    *(uint4*)&d_B2[(size_t)n * K9 + (r << 10) + ci8 * 8] = val;
}

// --------------------------------------------------------------- GEMM ------
// C(rows x Ncols) = A(rows, k-slice) @ B(Ncols, k-slice)^T, fp16, fp32 acc.
// 128x128 CTA tile, 4 warps as 2(m) x 2(n) -> warp tile 64x64.
#define TILE_B    (128 * 64)
#define OFF_A     0
#define OFF_B     (1 * TILE_B)
#define STG_B     (2 * TILE_B)
#define SMEM_TOTAL (STAGES * STG_B)         // 98304

__global__ __launch_bounds__(128, 2) void gemm_mma(
    const __half* __restrict__ A, const __half* __restrict__ B,
    float* __restrict__ C, int Ncols) {
    const int nparts = gridDim.z;
    const int KPr    = K9 / nparts;
    const int iters  = KPr / BK;
    const int rowsT  = gridDim.y * 128;

    extern __shared__ char smem[];
    const uint32_t smb = smem_u32(smem);
    const int tid  = threadIdx.x;
    const int lane = tid & 31;
    const int wid  = tid >> 5;
    const int wm   = wid >> 1;              // 0..1
    const int wn   = wid & 1;               // 0..1
    const int bym  = blockIdx.y * 128;
    const int bxn  = blockIdx.x * 128;
    const int kprt = blockIdx.z;

    const __half* pA = A + (size_t)bym * K9 + (size_t)kprt * KPr;
    const __half* pB = B + (size_t)bxn * K9 + (size_t)kprt * KPr;
    float* Cp = C + (size_t)kprt * rowsT * Ncols;

    // cp.async geometry: 512 chunks per matrix; 128 threads -> 4 per thread.
    int ldRow[4], ldC16[4];
    uint32_t ldDst[4];
#pragma unroll
    for (int t = 0; t < 4; t++) {
        int q = tid + 128 * t;
        ldRow[t] = q >> 2;
        ldC16[t] = q & 3;
        ldDst[t] = swz(ldRow[t], ldC16[t]);
    }

    auto issue_stage = [&](int stage, int k0) {
        uint32_t sb = smb + stage * STG_B;
#pragma unroll
        for (int t = 0; t < 4; t++) {
            size_t so = (size_t)ldRow[t] * K9 + k0 + ldC16[t] * 8;
            CP16(sb + OFF_A + ldDst[t], pA + so);
            CP16(sb + OFF_B + ldDst[t], pB + so);
        }
        CPCOMMIT();
    };

    float acc[4][8][4];
#pragma unroll
    for (int mt = 0; mt < 4; mt++)
#pragma unroll
        for (int nt = 0; nt < 8; nt++)
#pragma unroll
            for (int i = 0; i < 4; i++) acc[mt][nt][i] = 0.0f;

    const int a_row = wm * 64 + (lane & 15);         // + mt*16
    const int a_c   = lane >> 4;
    const int b_row = wn * 64 + ((lane >> 4) & 1) * 8 + (lane & 7);  // + g*16
    const int b_c   = (lane >> 3) & 1;

#pragma unroll
    for (int s = 0; s < STAGES - 1; s++) issue_stage(s, s * BK);

    int stage = 0;
    for (int it = 0; it < iters; it++) {
        CPWAIT(STAGES - 2);
        __syncthreads();
        if (it + STAGES - 1 < iters) {
            int ws = stage + STAGES - 1; if (ws >= STAGES) ws -= STAGES;
            issue_stage(ws, (it + STAGES - 1) * BK);
        } else {
            CPCOMMIT();
        }

        uint32_t sb = smb + stage * STG_B;
#pragma unroll
        for (int ks = 0; ks < 2; ks++) {
            uint32_t af[4][4];
#pragma unroll
            for (int mt = 0; mt < 4; mt++) {
                uint32_t ao = swz(a_row + mt * 16, ks * 2 + a_c);
                LDSM4(af[mt][0], af[mt][1], af[mt][2], af[mt][3], sb + OFF_A + ao);
            }
#pragma unroll
            for (int g = 0; g < 4; g++) {
                uint32_t bf[4];
                uint32_t bo = swz(b_row + g * 16, ks * 2 + b_c);
                LDSM4(bf[0], bf[1], bf[2], bf[3], sb + OFF_B + bo);
#pragma unroll
                for (int mt = 0; mt < 4; mt++) {
                    MMA16816(acc[mt][2 * g],     af[mt], bf[0], bf[1]);
                    MMA16816(acc[mt][2 * g + 1], af[mt], bf[2], bf[3]);
                }
            }
        }
        if (++stage == STAGES) stage = 0;
    }

#pragma unroll
    for (int mt = 0; mt < 4; mt++) {
        int r0 = bym + wm * 64 + mt * 16 + (lane >> 2);
#pragma unroll
        for (int nt = 0; nt < 8; nt++) {
            int c0 = bxn + wn * 64 + nt * 8 + (lane & 3) * 2;
            *(float2*)(Cp + (size_t)r0 * Ncols + c0) =
                make_float2(acc[mt][nt][0], acc[mt][nt][1]);
            *(float2*)(Cp + (size_t)(r0 + 8) * Ncols + c0) =
                make_float2(acc[mt][nt][2], acc[mt][nt][3]);
        }
    }
}

// ------------------------------------------------------------- combine -----
// Ht[(s,hw)][co] = relu(b1[co] + sum_e sum_p F^T[p][n_e][kd_e*1024+co]).
__global__ void combine1_kernel(const float* __restrict__ b1) {
    int idx = blockIdx.x * blockDim.x + threadIdx.x;
    if (idx >= NSLICE * HW * 256) return;
    int co4 = (idx & 255) << 2;
    int pix = idx >> 8;
    int hw  = pix % HW;
    int s   = pix / HW;

    int kd[3] = {-1, -1, -1};
    int gg[3] = {0, 0, 0};
    if (s < 8)       { kd[0] = 1; gg[0] = s - 4;  kd[1] = 2; gg[1] = s - 3; }
    else if (s < 17) { int g = s - 12;
                       kd[0] = 0; gg[0] = g; kd[1] = 1; gg[1] = g + 1;
                       kd[2] = 2; gg[2] = g + 2; }
    else             { int t = s - 17;
                       kd[0] = 0; gg[0] = t - 2; kd[1] = 1; gg[1] = t - 1; }

    float4 v = *(const float4*)(b1 + co4);
#pragma unroll
    for (int e = 0; e < 3; e++) {
        if (kd[e] >= 0 && gg[e] >= 0 && gg[e] < 8) {
            size_t off = ((size_t)gg[e] * HW + hw) * M1 + (kd[e] << 10) + co4;
#pragma unroll
            for (int p = 0; p < NKP1; p++) {
                float4 f = *(const float4*)(d_F + (size_t)p * N1P * M1 + off);
                v.x += f.x; v.y += f.y; v.z += f.z; v.w += f.w;
            }
        }
    }
    __half2 h0 = __floats2half2_rn(fmaxf(v.x, 0.0f), fmaxf(v.y, 0.0f));
    __half2 h1 = __floats2half2_rn(fmaxf(v.z, 0.0f), fmaxf(v.w, 0.0f));
    uint2 pk;
    pk.x = *(uint32_t*)&h0;
    pk.y = *(uint32_t*)&h1;
    *(uint2*)&d_Ht[(size_t)pix * 1024 + co4] = pk;
}

// ---------------------------------------------------------------- pool -----
__device__ __forceinline__ float c2sum(int j, int co, size_t idx) {
    size_t off = (size_t)(j * 512 + co) * N2P + idx;
    float v = 0.0f;
#pragma unroll
    for (int p = 0; p < NKP2; p++)
        v += d_C2[(size_t)p * M2 * N2P + off];
    return v;
}

__global__ void pool_kernel(const float* __restrict__ b2) {
    int t  = blockIdx.x >> 9;
    int co = blockIdx.x & 511;
    int s0 = t, s1 = t + 8, s2 = t + 9, s3 = t + 17;

    float m = -1e30f;
    for (int pos = threadIdx.x; pos < 4 * HW; pos += blockDim.x) {
        int d = pos / HW, hw = pos % HW;
        float v;
        if (d == 0)      v = c2sum(1, co, (size_t)s0 * HW + hw)
                           + c2sum(2, co, (size_t)s1 * HW + hw);
        else if (d == 1) v = c2sum(0, co, (size_t)s0 * HW + hw)
                           + c2sum(1, co, (size_t)s1 * HW + hw)
                           + c2sum(2, co, (size_t)s2 * HW + hw);
        else if (d == 2) v = c2sum(0, co, (size_t)s1 * HW + hw)
                           + c2sum(1, co, (size_t)s2 * HW + hw)
                           + c2sum(2, co, (size_t)s3 * HW + hw);
        else             v = c2sum(0, co, (size_t)s2 * HW + hw)
                           + c2sum(1, co, (size_t)s3 * HW + hw);
        m = fmaxf(m, v);
    }
    __shared__ float red[128];
    red[threadIdx.x] = m;
    __syncthreads();
    for (int sft = 64; sft > 0; sft >>= 1) {
        if (threadIdx.x < sft)
            red[threadIdx.x] = fmaxf(red[threadIdx.x], red[threadIdx.x + sft]);
        __syncthreads();
    }
    if (threadIdx.x == 0)
        d_pool[t * 512 + co] = fmaxf(b2[co] + red[0], 0.0f);
}

// ------------------------------------------------------------------ fc -----
__global__ void fc_kernel(const float* __restrict__ w1, const float* __restrict__ b1,
                          const float* __restrict__ w2, const float* __restrict__ b2,
                          const float* __restrict__ w3, const float* __restrict__ b3,
                          float* __restrict__ out) {
    int t = blockIdx.x;
    int j = threadIdx.x;
    __shared__ float x0[512], x1[512];
    x0[j] = d_pool[t * 512 + j];
    __syncthreads();

    float a = b1[j];
#pragma unroll 8
    for (int i = 0; i < 512; i++) a += x0[i] * w1[j * 512 + i];
    x1[j] = fmaxf(a, 0.0f);
    __syncthreads();

    a = b2[j];
#pragma unroll 8
    for (int i = 0; i < 512; i++) a += x1[i] * w2[j * 512 + i];
    __syncthreads();
    x0[j] = fmaxf(a, 0.0f);
    __syncthreads();

    if (j < 128) {
        a = b3[j];
#pragma unroll 8
        for (int i = 0; i < 512; i++) a += x0[i] * w3[j * 512 + i];
        out[t * 128 + j] = fmaxf(a, 0.0f);
    }
}

// -------------------------------------------------------------- launch -----
extern "C" void kernel_launch(void* const* d_in, const int* in_sizes, int n_in,
                              void* d_out, int out_size) {
    auto find = [&](int sz, int occ) -> const float* {
        int c = 0;
        for (int i = 0; i < n_in; i++)
            if (in_sizes[i] == sz) { if (c == occ) return (const float*)d_in[i]; c++; }
        return nullptr;
    };
    const float* videos = find(1605632, 0);
    const float* w1     = find(28311552, 0);
    const float* b1     = find(1024, 0);
    const float* w2     = find(14155776, 0);
    const float* b2     = find(512, 0);
    const float* l1w    = find(262144, 0);
    const float* l1b    = find(512, 1);
    const float* l2w    = find(262144, 1);
    const float* l2b    = find(512, 2);
    const float* l3w    = find(65536, 0);
    const float* l3b    = find(128, 0);
    float* out = (float*)d_out;

    cudaFuncSetAttribute(gemm_mma, cudaFuncAttributeMaxDynamicSharedMemorySize,
                         SMEM_TOTAL);

    const int TB = 256;
    __half *A1p, *A2p, *B1p, *B2p;
    float *Fp, *C2p;
    cudaGetSymbolAddress((void**)&A1p, d_A1);
    cudaGetSymbolAddress((void**)&A2p, d_A2);
    cudaGetSymbolAddress((void**)&B1p, d_B1);
    cudaGetSymbolAddress((void**)&B2p, d_B2);
    cudaGetSymbolAddress((void**)&Fp,  d_F);
    cudaGetSymbolAddress((void**)&C2p, d_C2);

    transpose_video_kernel<<<dim3(8, 7, 32), dim3(32, 8)>>>(videos);
    pack_w1_kernel<<<(1024 * 1024 + TB - 1) / TB, TB>>>(w1);
    pack_w2_kernel<<<(512 * 1024 + TB - 1) / TB, TB>>>(w2);
    im2col1_kernel<<<(N1P * 9 * 128 + TB - 1) / TB, TB>>>();

    // F^T = B1 @ A1^T : rows = pixels (N1P), cols = M1
    gemm_mma<<<dim3(M1 / 128, N1P / 128, NKP1), 128, SMEM_TOTAL>>>(
        B1p, A1p, Fp, M1);

    combine1_kernel<<<(NSLICE * HW * 256 + TB - 1) / TB, TB>>>(b1);
    im2col2_kernel<<<(N2P * 9 * 128 + TB - 1) / TB, TB>>>();

    // C2 = A2 @ B2^T : rows = M2, cols = N2P
    gemm_mma<<<dim3(N2P / 128, M2 / 128, NKP2), 128, SMEM_TOTAL>>>(
        A2p, B2p, C2p, N2P);

    pool_kernel<<<8 * 512, 128>>>(b2);
    fc_kernel<<<8, 512>>>(l1w, l1b, l2w, l2b, l3w, l3b, out);
}